// round 14
// baseline (speedup 1.0000x reference)
#include <cuda_runtime.h>
#include <cuda.h>
#include <cuda_fp16.h>
#include <math.h>
#include <stdint.h>

// ---------------- problem constants ----------------
#define BATCH   2
#define SEQLEN  4096
#define DMODEL  2048
#define DINNER  4096
#define NHEADS  64
#define HEADDIM 64
#define DSTATE  128
#define CHUNKL  64
#define NCHUNK  64
#define XPROJ   4416
#define NTOK    (BATCH*SEQLEN)   // 8192

// ---------------- scratch (device globals; no allocs allowed) ----------------
__device__ float g_xz[(size_t)NTOK * 2 * DINNER];     // fp32 (x_branch | z_branch)
__device__ float g_proj[(size_t)NTOK * XPROJ];
__device__ float g_dt[NTOK * NHEADS];
__device__ float g_dA[NTOK * NHEADS];
__device__ __half g_statesh[(size_t)BATCH * NCHUNK * NHEADS * HEADDIM * DSTATE];
// fp16 GEMM inputs
__device__ __half g_xh[(size_t)NTOK * DMODEL];
__device__ __half g_wih[(size_t)2 * DINNER * DMODEL];
__device__ __half g_wxh[(size_t)XPROJ * DINNER];
__device__ __half g_woh[(size_t)DMODEL * DINNER];
__device__ __half g_convh[(size_t)NTOK * DINNER];
__device__ __half g_Yh[(size_t)NTOK * DINNER];

// ============================================================================
// PTX helpers (baseline sm_80/sm_90 features only)
// ============================================================================
__device__ __forceinline__ uint32_t smem_u32(const void* p) {
    uint32_t a;
    asm("{ .reg .u64 t; cvta.to.shared.u64 t, %1; cvt.u32.u64 %0, t; }" : "=r"(a) : "l"(p));
    return a;
}

#define MBARRIER_INIT(addr, cnt) \
    asm volatile("mbarrier.init.shared.b64 [%0], %1;" :: "r"((uint32_t)(addr)), "r"((uint32_t)(cnt)) : "memory")

#define MBARRIER_EXPECT_TX(addr, bytes) \
    asm volatile("mbarrier.arrive.expect_tx.shared.b64 _, [%0], %1;" :: "r"((uint32_t)(addr)), "r"((uint32_t)(bytes)) : "memory")

#define MBARRIER_ARRIVE(addr) \
    asm volatile("mbarrier.arrive.shared.b64 _, [%0];" :: "r"((uint32_t)(addr)) : "memory")

#define MBARRIER_WAIT_PARITY(addr, parity) do {                                    \
    uint32_t _m = (uint32_t)(addr); uint32_t _p = (uint32_t)(parity); uint32_t _d; \
    asm volatile("{\n\t.reg .pred p;\n\t"                                          \
        "mbarrier.try_wait.parity.acquire.cta.shared::cta.b64 p, [%1], %2;\n\t"    \
        "selp.b32 %0, 1, 0, p;\n\t}"                                               \
        : "=r"(_d) : "r"(_m), "r"(_p) : "memory");                                 \
    if (!_d) {                                                                     \
        asm volatile("{\n\t.reg .pred P1;\n\t"                                     \
            "WL_%=:\n\t"                                                           \
            "mbarrier.try_wait.parity.acquire.cta.shared::cta.b64 P1, [%0], %1, 0x989680;\n\t" \
            "@P1 bra.uni WD_%=;\n\t"                                               \
            "bra.uni WL_%=;\n\t"                                                   \
            "WD_%=:\n\t}"                                                          \
            :: "r"(_m), "r"(_p) : "memory");                                       \
    }                                                                              \
} while (0)

#define FENCE_PROXY_ASYNC()   asm volatile("fence.proxy.async;" ::: "memory")

__device__ __forceinline__ void tma2d(uint32_t smem, const CUtensorMap* map,
                                      int cx, int cy, uint32_t mbar) {
    asm volatile(
        "cp.async.bulk.tensor.2d.shared::cta.global.tile.mbarrier::complete_tx::bytes "
        "[%0], [%1, {%2, %3}], [%4];"
        :: "r"(smem), "l"(map), "r"(cx), "r"(cy), "r"(mbar) : "memory");
}

#define LDMATRIX_X4(r0, r1, r2, r3, addr) \
    asm volatile("ldmatrix.sync.aligned.m8n8.x4.shared.b16 {%0,%1,%2,%3}, [%4];" \
        : "=r"(r0), "=r"(r1), "=r"(r2), "=r"(r3) : "r"(addr))

// mma m16n8k16 fp16 in, fp32 accum (sm_80+ baseline)
__device__ __forceinline__ void mma_f16(float* d, const uint32_t* a, const uint32_t* b) {
    asm volatile(
        "mma.sync.aligned.m16n8k16.row.col.f32.f16.f16.f32 "
        "{%0,%1,%2,%3}, {%4,%5,%6,%7}, {%8,%9}, {%0,%1,%2,%3};"
        : "+f"(d[0]), "+f"(d[1]), "+f"(d[2]), "+f"(d[3])
        : "r"(a[0]), "r"(a[1]), "r"(a[2]), "r"(a[3]), "r"(b[0]), "r"(b[1]));
}

__device__ __forceinline__ void split_h(float v, __half& hi, __half& lo) {
    hi = __float2half_rn(v);
    lo = __float2half_rn(v - __half2float(hi));
}

// ============================================================================
// fp16 HMMA GEMM: C[m,n] = sum_k A[m,k]*W[n,k]  (A,W fp16; C fp32)
// CTA tile 128x128, BK=64, 3-stage TMA pipeline (R7-proven refill structure:
// refill strictly AFTER the stage's own drain is confirmed — race-free).
// ============================================================================
#define GSTAGES 3
#define GBM 128
#define GBN 128
#define GBK 64
#define STAGE_BYTES  32768
#define SM_A(s)  ((s) * STAGE_BYTES)
#define SM_B(s)  ((s) * STAGE_BYTES + 16384)
#define MB_BASE  (GSTAGES * STAGE_BYTES)
#define MB_FULL(s)  (MB_BASE + 8 * (s))
#define MB_EMPTY(s) (MB_BASE + 32 + 8 * (s))
#define GEMM_SMEM   (MB_BASE + 128)

__global__ __launch_bounds__(256, 2) void gemm_f16_mma(
    const __grid_constant__ CUtensorMap tma_a,
    const __grid_constant__ CUtensorMap tma_b,
    float* __restrict__ C, int N, int K)
{
    extern __shared__ __align__(1024) char smem_raw[];
    uint32_t sb = smem_u32(smem_raw);
    const int tid = threadIdx.x;
    const int lane = tid & 31, wid = tid >> 5;
    const int wm = (wid & 1) * 64;
    const int wn = (wid >> 1) * 32;
    const int m0 = blockIdx.y * GBM;
    const int n0 = blockIdx.x * GBN;

    const int arow = lane & 15;
    const uint32_t ahi = lane >> 4;
    const int brow = (lane & 7) + ((lane >> 4) << 3);
    const uint32_t bhi = (lane >> 3) & 1;

    if (tid == 0) {
        for (int s = 0; s < GSTAGES; s++) {
            MBARRIER_INIT(sb + MB_FULL(s), 1);
            MBARRIER_INIT(sb + MB_EMPTY(s), 8);
        }
        FENCE_PROXY_ASYNC();
    }
    __syncthreads();

    const int KT = K / GBK;

    if (tid == 0) {
        for (int s = 0; s < GSTAGES; s++) {
            MBARRIER_EXPECT_TX(sb + MB_FULL(s), STAGE_BYTES);
            tma2d(sb + SM_A(s), &tma_a, s * GBK, m0, sb + MB_FULL(s));
            tma2d(sb + SM_B(s), &tma_b, s * GBK, n0, sb + MB_FULL(s));
        }
    }

    float acc[4][4][4];
#pragma unroll
    for (int i = 0; i < 4; i++)
#pragma unroll
        for (int j = 0; j < 4; j++)
#pragma unroll
            for (int v = 0; v < 4; v++) acc[i][j][v] = 0.f;

    int st = 0, ph = 0;
    for (int kt = 0; kt < KT; kt++) {
        MBARRIER_WAIT_PARITY(sb + MB_FULL(st), ph);
        const uint32_t sA = sb + SM_A(st);
        const uint32_t sB = sb + SM_B(st);

#pragma unroll
        for (int ks = 0; ks < 4; ks++) {
            uint32_t a[4][4], b[2][4];
#pragma unroll
            for (int mf = 0; mf < 4; mf++) {
                int row = wm + mf * 16 + arow;
                uint32_t addr = sA + row * 128 + ((((uint32_t)ks * 2 + ahi) ^ (row & 7)) << 4);
                LDMATRIX_X4(a[mf][0], a[mf][1], a[mf][2], a[mf][3], addr);
            }
#pragma unroll
            for (int nfp = 0; nfp < 2; nfp++) {
                int row = wn + nfp * 16 + brow;
                uint32_t addr = sB + row * 128 + ((((uint32_t)ks * 2 + bhi) ^ (row & 7)) << 4);
                LDMATRIX_X4(b[nfp][0], b[nfp][1], b[nfp][2], b[nfp][3], addr);
            }
#pragma unroll
            for (int mf = 0; mf < 4; mf++)
#pragma unroll
                for (int nf = 0; nf < 4; nf++)
                    mma_f16(acc[mf][nf], a[mf], &b[nf >> 1][(nf & 1) * 2]);
        }

        if (lane == 0) MBARRIER_ARRIVE(sb + MB_EMPTY(st));
        if (tid == 0 && kt + GSTAGES < KT) {
            MBARRIER_WAIT_PARITY(sb + MB_EMPTY(st), ph);
            MBARRIER_EXPECT_TX(sb + MB_FULL(st), STAGE_BYTES);
            tma2d(sb + SM_A(st), &tma_a, (kt + GSTAGES) * GBK, m0, sb + MB_FULL(st));
            tma2d(sb + SM_B(st), &tma_b, (kt + GSTAGES) * GBK, n0, sb + MB_FULL(st));
        }
        if (++st == GSTAGES) { st = 0; ph ^= 1; }
    }

    const int gID = lane >> 2, tg = lane & 3;
#pragma unroll
    for (int mf = 0; mf < 4; mf++) {
        const int row = m0 + wm + mf * 16 + gID;
#pragma unroll
        for (int nf = 0; nf < 4; nf++) {
            const int col = n0 + wn + nf * 8 + tg * 2;
            if (col < N) {
                *(float2*)&C[(size_t)row * N + col] = make_float2(acc[mf][nf][0], acc[mf][nf][1]);
                *(float2*)&C[(size_t)(row + 8) * N + col] = make_float2(acc[mf][nf][2], acc[mf][nf][3]);
            }
        }
    }
}

// ---------------- fp32 -> fp16 RN conversion ----------------
__global__ void to_half_kernel(const float4* __restrict__ in, uint2* __restrict__ out, int n4)
{
    int i = blockIdx.x * blockDim.x + threadIdx.x;
    if (i < n4) {
        float4 v = in[i];
        __half2 h0 = __floats2half2_rn(v.x, v.y);
        __half2 h1 = __floats2half2_rn(v.z, v.w);
        uint2 r;
        r.x = *reinterpret_cast<uint32_t*>(&h0);
        r.y = *reinterpret_cast<uint32_t*>(&h1);
        out[i] = r;
    }
}

// ---------------- depthwise causal conv (D_CONV=4) + bias + SiLU -> fp16 -----
// 2 channels per thread (vectorized; per-channel math identical to scalar).
__global__ void conv_silu_kernel(const float* __restrict__ convw,
                                 const float* __restrict__ convb)
{
    int idx2 = blockIdx.x * blockDim.x + threadIdx.x;        // pair index
    if (idx2 >= NTOK * DINNER / 2) return;
    int c = (idx2 << 1) & (DINNER - 1);                      // even channel
    int tok = idx2 >> 11;                                    // /(DINNER/2)
    int t = tok & (SEQLEN - 1);
    float2 bias = *(const float2*)&convb[c];
    float y0 = bias.x, y1 = bias.y;
    float2 w0 = *(const float2*)&convw[c * 4];               // convw[c][0..1]
    float2 w1 = *(const float2*)&convw[c * 4 + 2];           // convw[c][2..3]
    float2 w2 = *(const float2*)&convw[(c + 1) * 4];         // convw[c+1][0..1]
    float2 w3 = *(const float2*)&convw[(c + 1) * 4 + 2];     // convw[c+1][2..3]
    float wA[4] = { w0.x, w0.y, w1.x, w1.y };
    float wB[4] = { w2.x, w2.y, w3.x, w3.y };
#pragma unroll
    for (int j = 0; j < 4; j++) {
        int tt = t - 3 + j;
        if (tt >= 0) {
            float2 xv = *(const float2*)&g_xz[(size_t)(tok - 3 + j) * (2 * DINNER) + c];
            y0 = fmaf(wA[j], xv.x, y0);
            y1 = fmaf(wB[j], xv.y, y1);
        }
    }
    float s0 = y0 / (1.f + expf(-y0));
    float s1 = y1 / (1.f + expf(-y1));
    *(__half2*)&g_convh[(size_t)tok * DINNER + c] = __floats2half2_rn(s0, s1);
}

// ---------------- dt projection + softplus; dA = -exp(A_log)*dt --------------
__global__ __launch_bounds__(256) void dt_kernel(const float* __restrict__ dtw,
                                                 const float* __restrict__ dtb,
                                                 const float* __restrict__ A_log)
{
    int sub = threadIdx.x >> 6;
    int h = threadIdx.x & 63;
    int tok = blockIdx.x * 4 + sub;
    __shared__ float raw[4][64];
    raw[sub][h] = g_proj[(size_t)tok * XPROJ + DINNER + h];
    __syncthreads();
    float acc = dtb[h];
#pragma unroll
    for (int k = 0; k < 64; k++) acc = fmaf(dtw[h * 64 + k], raw[sub][k], acc);
    float dt = (acc > 20.f) ? acc : log1pf(expf(acc));
    g_dt[tok * 64 + h] = dt;
    g_dA[tok * 64 + h] = -expf(A_log[h]) * dt;
}

// ============================================================================
// per-chunk local states via split-operand MMA:
// S[p][n] = sum_t Xd[t][p] * B[t][n];  Xd split hi/lo (22-bit effective)
// ============================================================================
#define SST_SBT   0                        // halves
#define SST_SXT   (128 * 72)               // 9216
#define SST_SXTL  (SST_SXT + 64 * 72)      // 13824
#define SST_SA    (SST_SXTL + 64 * 72)     // 18432 halves
#define SST_SMEM  ((SST_SA + 128) * 2)     // bytes

__global__ __launch_bounds__(256) void ssd_states_kernel()
{
    extern __shared__ __align__(16) __half smh[];
    __half* sBT   = smh + SST_SBT;
    __half* sXdT  = smh + SST_SXT;
    __half* sXdTL = smh + SST_SXTL;
    float* sa = (float*)(smh + SST_SA);
    int bid = blockIdx.x;
    int h = bid & 63, c = (bid >> 6) & 63, b = bid >> 12;
    int tok0 = b * SEQLEN + c * CHUNKL;
    int tid = threadIdx.x;
    const int lane = tid & 31, wid = tid >> 5;

    if (tid < 64) sa[tid] = g_dA[(tok0 + tid) * NHEADS + h];
    __syncthreads();
    if (tid == 0) { float s = 0.f; for (int t = 0; t < 64; t++) { s += sa[t]; sa[t] = s; } }
    __syncthreads();
    float alast = sa[63];

    for (int i = tid; i < 8192; i += 256) {
        int t = i >> 7, n = i & 127;
        sBT[n * 72 + t] = __float2half_rn(g_proj[(size_t)(tok0 + t) * XPROJ + (DINNER + NHEADS) + n]);
    }
    for (int i = tid; i < 4096; i += 256) {
        int t = i >> 6, p = i & 63;
        float v = g_proj[(size_t)(tok0 + t) * XPROJ + h * 64 + p]
                * g_dt[(tok0 + t) * NHEADS + h] * expf(alast - sa[t]);
        __half hi, lo; split_h(v, hi, lo);
        sXdT[p * 72 + t] = hi;
        sXdTL[p * 72 + t] = lo;
    }
    __syncthreads();

    const int arow = lane & 15;
    const uint32_t ahx = lane >> 4;
    const int brow = (lane & 7) + ((lane >> 4) << 3);
    const uint32_t bhx = (lane >> 3) & 1;
    const int wm = (wid & 1) * 32;     // p
    const int wn = (wid >> 1) * 32;    // n

    uint32_t xb = smem_u32(sXdT), xlb = smem_u32(sXdTL), bb = smem_u32(sBT);
    float acc[2][4][4];
#pragma unroll
    for (int i = 0; i < 2; i++)
#pragma unroll
        for (int j = 0; j < 4; j++)
#pragma unroll
            for (int v = 0; v < 4; v++) acc[i][j][v] = 0.f;

#pragma unroll
    for (int ks = 0; ks < 4; ks++) {
        uint32_t a[2][4], al[2][4], bfr[2][4];
#pragma unroll
        for (int mf = 0; mf < 2; mf++) {
            int row = wm + mf * 16 + arow;
            LDMATRIX_X4(a[mf][0], a[mf][1], a[mf][2], a[mf][3],
                        xb + row * 144 + ((uint32_t)ks * 2 + ahx) * 16);
            LDMATRIX_X4(al[mf][0], al[mf][1], al[mf][2], al[mf][3],
                        xlb + row * 144 + ((uint32_t)ks * 2 + ahx) * 16);
        }
#pragma unroll
        for (int nfp = 0; nfp < 2; nfp++) {
            int row = wn + nfp * 16 + brow;
            LDMATRIX_X4(bfr[nfp][0], bfr[nfp][1], bfr[nfp][2], bfr[nfp][3],
                        bb + row * 144 + ((uint32_t)ks * 2 + bhx) * 16);
        }
#pragma unroll
        for (int mf = 0; mf < 2; mf++)
#pragma unroll
            for (int nf = 0; nf < 4; nf++) {
                mma_f16(acc[mf][nf], a[mf], &bfr[nf >> 1][(nf & 1) * 2]);
                mma_f16(acc[mf][nf], al[mf], &bfr[nf >> 1][(nf & 1) * 2]);
            }
    }

    const int gID = lane >> 2, tg = lane & 3;
    size_t outbase = ((size_t)((b * 64 + c) * 64 + h)) * 8192;
#pragma unroll
    for (int mf = 0; mf < 2; mf++) {
        int p = wm + mf * 16 + gID;
#pragma unroll
        for (int nf = 0; nf < 4; nf++) {
            int n = wn + nf * 8 + tg * 2;
            *(__half2*)&g_statesh[outbase + (size_t)p * 128 + n] =
                __floats2half2_rn(acc[mf][nf][0], acc[mf][nf][1]);
            *(__half2*)&g_statesh[outbase + (size_t)(p + 8) * 128 + n] =
                __floats2half2_rn(acc[mf][nf][2], acc[mf][nf][3]);
        }
    }
}

// ---------------- inter-chunk sequential scan (fp16 states, fp32 carry) ------
__global__ __launch_bounds__(256) void ssd_scan_kernel()
{
    __shared__ float alast[64];
    int blk = blockIdx.x;
    int slice = blk & 7;
    int bh = blk >> 3;
    int b = bh >> 6, h = bh & 63;
    int tid = threadIdx.x;
    if (tid < 64) {
        int c = tid;
        int tok0 = b * SEQLEN + c * CHUNKL;
        float s = 0.f;
        for (int t = 0; t < 64; t++) s += g_dA[(tok0 + t) * NHEADS + h];
        alast[c] = expf(s);
    }
    __syncthreads();
    float run0 = 0.f, run1 = 0.f, run2 = 0.f, run3 = 0.f;
    int off = slice * 1024 + tid * 4;
    for (int c = 0; c < 64; c++) {
        size_t base = ((size_t)((b * 64 + c) * 64 + h)) * 8192 + off;
        float dec = alast[c];
        uint2 v = *(const uint2*)&g_statesh[base];
        __half2 l0 = *reinterpret_cast<__half2*>(&v.x);
        __half2 l1 = *reinterpret_cast<__half2*>(&v.y);
        float2 f0 = __half22float2(l0);
        float2 f1 = __half22float2(l1);
        __half2 e0 = __floats2half2_rn(run0, run1);
        __half2 e1 = __floats2half2_rn(run2, run3);
        uint2 w;
        w.x = *reinterpret_cast<uint32_t*>(&e0);
        w.y = *reinterpret_cast<uint32_t*>(&e1);
        *(uint2*)&g_statesh[base] = w;
        run0 = fmaf(dec, run0, f0.x);
        run1 = fmaf(dec, run1, f0.y);
        run2 = fmaf(dec, run2, f1.x);
        run3 = fmaf(dec, run3, f1.y);
    }
}

// ============================================================================
// SSD output via split-operand MMA:
//  G = mask * (C @ B^T) * decay   (C split hi/lo; G stored hi/lo)
//  Y = G @ X  +  exp(sa[t]) * (C @ Sin^T)  + X*D, gated by silu(z)
// ============================================================================
#define SO_C    0
#define SO_CLO  (64 * 136)               // 8704
#define SO_B    (2 * 64 * 136)           // 17408
#define SO_SIN  (3 * 64 * 136)           // 26112
#define SO_XT   (4 * 64 * 136)           // 34816
#define SO_G    (SO_XT + 64 * 72)        // 39424
#define SO_GLO  (SO_G + 64 * 72)         // 44032
#define SO_SA   (SO_GLO + 64 * 72)       // 48640 halves
#define SO_SMEM ((SO_SA + 128) * 2)      // 97536 bytes

__global__ __launch_bounds__(256) void ssd_out_kernel(const float* __restrict__ Dp)
{
    extern __shared__ __align__(16) __half smh[];
    __half* sC   = smh + SO_C;
    __half* sCL  = smh + SO_CLO;
    __half* sB   = smh + SO_B;
    __half* sSin = smh + SO_SIN;
    __half* sXT  = smh + SO_XT;
    __half* sG   = smh + SO_G;
    __half* sGL  = smh + SO_GLO;
    float*  sa   = (float*)(smh + SO_SA);

    int bid = blockIdx.x;
    int h = bid & 63, c = (bid >> 6) & 63, b = bid >> 12;
    int tok0 = b * SEQLEN + c * CHUNKL;
    int tid = threadIdx.x;
    const int lane = tid & 31, wid = tid >> 5;

    if (tid < 64) sa[tid] = g_dA[(tok0 + tid) * NHEADS + h];
    __syncthreads();
    if (tid == 0) { float s = 0.f; for (int t = 0; t < 64; t++) { s += sa[t]; sa[t] = s; } }

    size_t sbase = ((size_t)((b * 64 + c) * 64 + h)) * 8192;
    for (int i = tid; i < 8192; i += 256) {
        int t = i >> 7, n = i & 127;
        float cv = g_proj[(size_t)(tok0 + t) * XPROJ + (DINNER + NHEADS + DSTATE) + n];
        __half chi, clo; split_h(cv, chi, clo);
        sC[t * 136 + n]  = chi;
        sCL[t * 136 + n] = clo;
        sB[t * 136 + n]  = __float2half_rn(g_proj[(size_t)(tok0 + t) * XPROJ + (DINNER + NHEADS) + n]);
        sSin[t * 136 + n] = g_statesh[sbase + i];    // t here is p
    }
    for (int i = tid; i < 4096; i += 256) {
        int t = i >> 6, p = i & 63;
        float v = g_proj[(size_t)(tok0 + t) * XPROJ + h * 64 + p] * g_dt[(tok0 + t) * NHEADS + h];
        sXT[p * 72 + t] = __float2half_rn(v);
    }
    __syncthreads();

    const int arow = lane & 15;
    const uint32_t ahx = lane >> 4;
    const int brow = (lane & 7) + ((lane >> 4) << 3);
    const uint32_t bhx = (lane >> 3) & 1;
    const int gID = lane >> 2, tg = lane & 3;

    uint32_t cb = smem_u32(sC), clb = smem_u32(sCL), bb = smem_u32(sB), sinb = smem_u32(sSin);
    uint32_t xtb = smem_u32(sXT), gb = smem_u32(sG), glb = smem_u32(sGL);

    // ---- phase 1: G = (Chi+Clo) @ B^T, masked + decay, store hi/lo fp16 ----
    {
        const int wt = (wid & 3) * 16;     // t
        const int ws = (wid >> 2) * 32;    // s
        float gacc[4][4];
#pragma unroll
        for (int j = 0; j < 4; j++)
#pragma unroll
            for (int v = 0; v < 4; v++) gacc[j][v] = 0.f;

#pragma unroll
        for (int ks = 0; ks < 8; ks++) {
            uint32_t a[4], al[4], bfr[2][4];
            {
                int row = wt + arow;
                LDMATRIX_X4(a[0], a[1], a[2], a[3], cb + row * 272 + ((uint32_t)ks * 2 + ahx) * 16);
                LDMATRIX_X4(al[0], al[1], al[2], al[3], clb + row * 272 + ((uint32_t)ks * 2 + ahx) * 16);
            }
#pragma unroll
            for (int nfp = 0; nfp < 2; nfp++) {
                int row = ws + nfp * 16 + brow;
                LDMATRIX_X4(bfr[nfp][0], bfr[nfp][1], bfr[nfp][2], bfr[nfp][3],
                            bb + row * 272 + ((uint32_t)ks * 2 + bhx) * 16);
            }
#pragma unroll
            for (int nf = 0; nf < 4; nf++) {
                mma_f16(gacc[nf], a, &bfr[nf >> 1][(nf & 1) * 2]);
                mma_f16(gacc[nf], al, &bfr[nf >> 1][(nf & 1) * 2]);
            }
        }

        int t0 = wt + gID, t1 = t0 + 8;
        float e0 = sa[t0], e1 = sa[t1];
#pragma unroll
        for (int nf = 0; nf < 4; nf++) {
            int s0 = ws + nf * 8 + tg * 2;
            float es0 = sa[s0], es1 = sa[s0 + 1];
            float v00 = (s0     <= t0) ? gacc[nf][0] * expf(e0 - es0) : 0.f;
            float v01 = (s0 + 1 <= t0) ? gacc[nf][1] * expf(e0 - es1) : 0.f;
            float v10 = (s0     <= t1) ? gacc[nf][2] * expf(e1 - es0) : 0.f;
            float v11 = (s0 + 1 <= t1) ? gacc[nf][3] * expf(e1 - es1) : 0.f;
            __half h00, l00, h01, l01, h10, l10, h11, l11;
            split_h(v00, h00, l00); split_h(v01, h01, l01);
            split_h(v10, h10, l10); split_h(v11, h11, l11);
            *(__half2*)&sG[t0 * 72 + s0]  = __halves2half2(h00, h01);
            *(__half2*)&sGL[t0 * 72 + s0] = __halves2half2(l00, l01);
            *(__half2*)&sG[t1 * 72 + s0]  = __halves2half2(h10, h11);
            *(__half2*)&sGL[t1 * 72 + s0] = __halves2half2(l10, l11);
        }
    }
    __syncthreads();

    // ---- phase 2: Y = (Ghi+Glo)@X + exp(sa[t]) * ((Chi+Clo)@Sin^T) ----
    {
        const int wt = (wid & 3) * 16;     // t
        const int wp = (wid >> 2) * 32;    // p
        float accd[4][4], acco[4][4];
#pragma unroll
        for (int j = 0; j < 4; j++)
#pragma unroll
            for (int v = 0; v < 4; v++) { accd[j][v] = 0.f; acco[j][v] = 0.f; }

        // diag: A = G[t][s] (k=s,64) split, B = sXT[p][s]
#pragma unroll
        for (int ks = 0; ks < 4; ks++) {
            uint32_t a[4], al[4], bfr[2][4];
            {
                int row = wt + arow;
                LDMATRIX_X4(a[0], a[1], a[2], a[3], gb + row * 144 + ((uint32_t)ks * 2 + ahx) * 16);
                LDMATRIX_X4(al[0], al[1], al[2], al[3], glb + row * 144 + ((uint32_t)ks * 2 + ahx) * 16);
            }
#pragma unroll
            for (int nfp = 0; nfp < 2; nfp++) {
                int row = wp + nfp * 16 + brow;
                LDMATRIX_X4(bfr[nfp][0], bfr[nfp][1], bfr[nfp][2], bfr[nfp][3],
                            xtb + row * 144 + ((uint32_t)ks * 2 + bhx) * 16);
            }
#pragma unroll
            for (int nf = 0; nf < 4; nf++) {
                mma_f16(accd[nf], a, &bfr[nf >> 1][(nf & 1) * 2]);
                mma_f16(accd[nf], al, &bfr[nf >> 1][(nf & 1) * 2]);
            }
        }

        // off: A = C[t][n] (k=n,128) split, B = sSin[p][n]
#pragma unroll
        for (int ks = 0; ks < 8; ks++) {
            uint32_t a[4], al[4], bfr[2][4];
            {
                int row = wt + arow;
                LDMATRIX_X4(a[0], a[1], a[2], a[3], cb + row * 272 + ((uint32_t)ks * 2 + ahx) * 16);
                LDMATRIX_X4(al[0], al[1], al[2], al[3], clb + row * 272 + ((uint32_t)ks * 2 + ahx) * 16);
            }
#pragma unroll
            for (int nfp = 0; nfp < 2; nfp++) {
                int row = wp + nfp * 16 + brow;
                LDMATRIX_X4(bfr[nfp][0], bfr[nfp][1], bfr[nfp][2], bfr[nfp][3],
                            sinb + row * 272 + ((uint32_t)ks * 2 + bhx) * 16);
            }
#pragma unroll
            for (int nf = 0; nf < 4; nf++) {
                mma_f16(acco[nf], a, &bfr[nf >> 1][(nf & 1) * 2]);
                mma_f16(acco[nf], al, &bfr[nf >> 1][(nf & 1) * 2]);
            }
        }

        float dh = Dp[h];
        int t0 = wt + gID;
#pragma unroll
        for (int r = 0; r < 2; r++) {
            int t = t0 + r * 8;
            int tok = tok0 + t;
            float sc = expf(sa[t]);
            const float* projX = &g_proj[(size_t)tok * XPROJ + h * 64];
            const float* zrow = &g_xz[(size_t)tok * (2 * DINNER) + DINNER + h * 64];
            __half* yrow = &g_Yh[(size_t)tok * DINNER + h * 64];
#pragma unroll
            for (int nf = 0; nf < 4; nf++) {
                int p = wp + nf * 8 + tg * 2;
                float y0 = accd[nf][r * 2 + 0] + acco[nf][r * 2 + 0] * sc + projX[p] * dh;
                float y1 = accd[nf][r * 2 + 1] + acco[nf][r * 2 + 1] * sc + projX[p + 1] * dh;
                float z0 = zrow[p], z1 = zrow[p + 1];
                y0 *= z0 / (1.f + expf(-z0));
                y1 *= z1 / (1.f + expf(-z1));
                *(__half2*)&yrow[p] = __floats2half2_rn(y0, y1);
            }
        }
    }
}

// ============================================================================
// host side
// ============================================================================
typedef CUresult (*PFN_encode)(CUtensorMap*, CUtensorMapDataType, cuuint32_t, void*,
    const cuuint64_t*, const cuuint64_t*, const cuuint32_t*, const cuuint32_t*,
    CUtensorMapInterleave, CUtensorMapSwizzle, CUtensorMapL2promotion, CUtensorMapFloatOOBfill);

static PFN_encode get_encoder() {
    void* p = nullptr;
    cudaDriverEntryPointQueryResult qr;
#if CUDART_VERSION >= 12050
    cudaGetDriverEntryPointByVersion("cuTensorMapEncodeTiled", &p, 12000, cudaEnableDefault, &qr);
#else
    cudaGetDriverEntryPoint("cuTensorMapEncodeTiled", &p, cudaEnableDefault, &qr);
#endif
    return (PFN_encode)p;
}

static void make_map_h(PFN_encode enc, CUtensorMap* m, const void* ptr,
                       uint64_t d0, uint64_t d1, uint32_t b0, uint32_t b1)
{
    cuuint64_t dims[2] = { d0, d1 };
    cuuint64_t strides[1] = { d0 * 2 };
    cuuint32_t box[2] = { b0, b1 };
    cuuint32_t es[2] = { 1, 1 };
    enc(m, CU_TENSOR_MAP_DATA_TYPE_FLOAT16, 2, (void*)ptr, dims, strides, box, es,
        CU_TENSOR_MAP_INTERLEAVE_NONE, CU_TENSOR_MAP_SWIZZLE_128B,
        CU_TENSOR_MAP_L2_PROMOTION_L2_128B, CU_TENSOR_MAP_FLOAT_OOB_FILL_NONE);
}

extern "C" void kernel_launch(void* const* d_in, const int* in_sizes, int n_in,
                              void* d_out, int out_size)
{
    const float* x          = (const float*)d_in[0];
    const float* conv_w     = (const float*)d_in[2];
    const float* conv_b     = (const float*)d_in[3];
    const float* dt_proj_w  = (const float*)d_in[5];
    const float* dt_proj_b  = (const float*)d_in[6];
    const float* A_log      = (const float*)d_in[7];
    const float* Dp         = (const float*)d_in[8];
    float* out = (float*)d_out;

    void *p_xh, *p_wih, *p_wxh, *p_woh, *p_convh, *p_Yh;
    float *p_xz, *p_proj;
    cudaGetSymbolAddress(&p_xh,    g_xh);
    cudaGetSymbolAddress(&p_wih,   g_wih);
    cudaGetSymbolAddress(&p_wxh,   g_wxh);
    cudaGetSymbolAddress(&p_woh,   g_woh);
    cudaGetSymbolAddress(&p_convh, g_convh);
    cudaGetSymbolAddress(&p_Yh,    g_Yh);
    cudaGetSymbolAddress((void**)&p_xz,   g_xz);
    cudaGetSymbolAddress((void**)&p_proj, g_proj);

    cudaFuncSetAttribute(gemm_f16_mma,      cudaFuncAttributeMaxDynamicSharedMemorySize, GEMM_SMEM);
    cudaFuncSetAttribute(ssd_states_kernel, cudaFuncAttributeMaxDynamicSharedMemorySize, SST_SMEM);
    cudaFuncSetAttribute(ssd_out_kernel,    cudaFuncAttributeMaxDynamicSharedMemorySize, SO_SMEM);

    PFN_encode enc = get_encoder();
    CUtensorMap mA1, mB1, mA2, mB2, mA3, mB3;
    make_map_h(enc, &mA1, p_xh,    DMODEL, NTOK,       GBK, GBM);
    make_map_h(enc, &mB1, p_wih,   DMODEL, 2 * DINNER, GBK, GBN);
    make_map_h(enc, &mA2, p_convh, DINNER, NTOK,       GBK, GBM);
    make_map_h(enc, &mB2, p_wxh,   DINNER, XPROJ,      GBK, GBN);
    make_map_h(enc, &mA3, p_Yh,    DINNER, NTOK,       GBK, GBM);
    make_map_h(enc, &mB3, p_woh,   DINNER, DMODEL,     GBK, GBN);

    to_half_kernel<<<(NTOK * DMODEL / 4 + 255) / 256, 256>>>((const float4*)x, (uint2*)p_xh, NTOK * DMODEL / 4);
    to_half_kernel<<<(2 * DINNER * DMODEL / 4 + 255) / 256, 256>>>((const float4*)d_in[1], (uint2*)p_wih, 2 * DINNER * DMODEL / 4);
    to_half_kernel<<<((int)((size_t)XPROJ * DINNER / 4) + 255) / 256, 256>>>((const float4*)d_in[4], (uint2*)p_wxh, (int)((size_t)XPROJ * DINNER / 4));
    to_half_kernel<<<(DMODEL * DINNER / 4 + 255) / 256, 256>>>((const float4*)d_in[9], (uint2*)p_woh, DMODEL * DINNER / 4);

    // 1) xz = x @ in_proj_w^T  (fp32 out — dt path amplifies rounding via exp(cumsum))
    gemm_f16_mma<<<dim3(2 * DINNER / GBN, NTOK / GBM), 256, GEMM_SMEM>>>(mA1, mB1, p_xz, 2 * DINNER, DMODEL);
    // 2) depthwise conv + bias + silu (fp16 out, 2 ch/thread)
    conv_silu_kernel<<<(NTOK * DINNER / 2) / 256, 256>>>(conv_w, conv_b);
    // 3) proj = conv @ x_proj_w^T (fp32 out)
    gemm_f16_mma<<<dim3((XPROJ + GBN - 1) / GBN, NTOK / GBM), 256, GEMM_SMEM>>>(mA2, mB2, p_proj, XPROJ, DINNER);
    // 4) dt
    dt_kernel<<<NTOK / 4, 256>>>(dt_proj_w, dt_proj_b, A_log);
    // 5) per-chunk local states (split MMA, fp16 states out)
    ssd_states_kernel<<<BATCH * NCHUNK * NHEADS, 256, SST_SMEM>>>();
    // 6) inter-chunk scan (fp16 states, fp32 carry)
    ssd_scan_kernel<<<BATCH * NHEADS * 8, 256>>>();
    // 7) SSD output + gating (split MMA, fp16 out)
    ssd_out_kernel<<<BATCH * NCHUNK * NHEADS, 256, SO_SMEM>>>(Dp);
    // 8) out = Y @ out_proj_w^T (fp32 out)
    gemm_f16_mma<<<dim3(DMODEL / GBN, NTOK / GBM), 256, GEMM_SMEM>>>(mA3, mB3, out, DMODEL, DINNER);
}

// round 15
// speedup vs baseline: 1.0002x; 1.0002x over previous
#include <cuda_runtime.h>
#include <cuda.h>
#include <cuda_fp16.h>
#include <math.h>
#include <stdint.h>

// ---------------- problem constants ----------------
#define BATCH   2
#define SEQLEN  4096
#define DMODEL  2048
#define DINNER  4096
#define NHEADS  64
#define HEADDIM 64
#define DSTATE  128
#define CHUNKL  64
#define NCHUNK  64
#define XPROJ   4416
#define NTOK    (BATCH*SEQLEN)   // 8192

// ---------------- scratch (device globals; no allocs allowed) ----------------
__device__ float g_xz[(size_t)NTOK * 2 * DINNER];     // fp32 (x_branch | z_branch)
__device__ float g_proj[(size_t)NTOK * XPROJ];
__device__ float g_dt[NTOK * NHEADS];
__device__ float g_dA[NTOK * NHEADS];
__device__ __half g_statesh[(size_t)BATCH * NCHUNK * NHEADS * HEADDIM * DSTATE];
// fp16 GEMM inputs
__device__ __half g_xh[(size_t)NTOK * DMODEL];
__device__ __half g_wih[(size_t)2 * DINNER * DMODEL];
__device__ __half g_wxh[(size_t)XPROJ * DINNER];
__device__ __half g_woh[(size_t)DMODEL * DINNER];
__device__ __half g_convh[(size_t)NTOK * DINNER];
__device__ __half g_Yh[(size_t)NTOK * DINNER];

// ============================================================================
// PTX helpers (baseline sm_80/sm_90 features only)
// ============================================================================
__device__ __forceinline__ uint32_t smem_u32(const void* p) {
    uint32_t a;
    asm("{ .reg .u64 t; cvta.to.shared.u64 t, %1; cvt.u32.u64 %0, t; }" : "=r"(a) : "l"(p));
    return a;
}

#define MBARRIER_INIT(addr, cnt) \
    asm volatile("mbarrier.init.shared.b64 [%0], %1;" :: "r"((uint32_t)(addr)), "r"((uint32_t)(cnt)) : "memory")

#define MBARRIER_EXPECT_TX(addr, bytes) \
    asm volatile("mbarrier.arrive.expect_tx.shared.b64 _, [%0], %1;" :: "r"((uint32_t)(addr)), "r"((uint32_t)(bytes)) : "memory")

#define MBARRIER_ARRIVE(addr) \
    asm volatile("mbarrier.arrive.shared.b64 _, [%0];" :: "r"((uint32_t)(addr)) : "memory")

#define MBARRIER_WAIT_PARITY(addr, parity) do {                                    \
    uint32_t _m = (uint32_t)(addr); uint32_t _p = (uint32_t)(parity); uint32_t _d; \
    asm volatile("{\n\t.reg .pred p;\n\t"                                          \
        "mbarrier.try_wait.parity.acquire.cta.shared::cta.b64 p, [%1], %2;\n\t"    \
        "selp.b32 %0, 1, 0, p;\n\t}"                                               \
        : "=r"(_d) : "r"(_m), "r"(_p) : "memory");                                 \
    if (!_d) {                                                                     \
        asm volatile("{\n\t.reg .pred P1;\n\t"                                     \
            "WL_%=:\n\t"                                                           \
            "mbarrier.try_wait.parity.acquire.cta.shared::cta.b64 P1, [%0], %1, 0x989680;\n\t" \
            "@P1 bra.uni WD_%=;\n\t"                                               \
            "bra.uni WL_%=;\n\t"                                                   \
            "WD_%=:\n\t}"                                                          \
            :: "r"(_m), "r"(_p) : "memory");                                       \
    }                                                                              \
} while (0)

#define FENCE_PROXY_ASYNC()   asm volatile("fence.proxy.async;" ::: "memory")

__device__ __forceinline__ void tma2d(uint32_t smem, const CUtensorMap* map,
                                      int cx, int cy, uint32_t mbar) {
    asm volatile(
        "cp.async.bulk.tensor.2d.shared::cta.global.tile.mbarrier::complete_tx::bytes "
        "[%0], [%1, {%2, %3}], [%4];"
        :: "r"(smem), "l"(map), "r"(cx), "r"(cy), "r"(mbar) : "memory");
}

#define LDMATRIX_X4(r0, r1, r2, r3, addr) \
    asm volatile("ldmatrix.sync.aligned.m8n8.x4.shared.b16 {%0,%1,%2,%3}, [%4];" \
        : "=r"(r0), "=r"(r1), "=r"(r2), "=r"(r3) : "r"(addr))

// mma m16n8k16 fp16 in, fp32 accum (sm_80+ baseline)
__device__ __forceinline__ void mma_f16(float* d, const uint32_t* a, const uint32_t* b) {
    asm volatile(
        "mma.sync.aligned.m16n8k16.row.col.f32.f16.f16.f32 "
        "{%0,%1,%2,%3}, {%4,%5,%6,%7}, {%8,%9}, {%0,%1,%2,%3};"
        : "+f"(d[0]), "+f"(d[1]), "+f"(d[2]), "+f"(d[3])
        : "r"(a[0]), "r"(a[1]), "r"(a[2]), "r"(a[3]), "r"(b[0]), "r"(b[1]));
}

__device__ __forceinline__ void split_h(float v, __half& hi, __half& lo) {
    hi = __float2half_rn(v);
    lo = __float2half_rn(v - __half2float(hi));
}

// ============================================================================
// fp16 HMMA GEMM: C[m,n] = sum_k A[m,k]*W[n,k]  (A,W fp16; C fp32)
// CTA tile 128x128, BK=64, 3-stage TMA pipeline (R7-proven refill structure:
// refill strictly AFTER the stage's own drain is confirmed — race-free).
// ============================================================================
#define GSTAGES 3
#define GBM 128
#define GBN 128
#define GBK 64
#define STAGE_BYTES  32768
#define SM_A(s)  ((s) * STAGE_BYTES)
#define SM_B(s)  ((s) * STAGE_BYTES + 16384)
#define MB_BASE  (GSTAGES * STAGE_BYTES)
#define MB_FULL(s)  (MB_BASE + 8 * (s))
#define MB_EMPTY(s) (MB_BASE + 32 + 8 * (s))
#define GEMM_SMEM   (MB_BASE + 128)

__global__ __launch_bounds__(256, 2) void gemm_f16_mma(
    const __grid_constant__ CUtensorMap tma_a,
    const __grid_constant__ CUtensorMap tma_b,
    float* __restrict__ C, int N, int K)
{
    extern __shared__ __align__(1024) char smem_raw[];
    uint32_t sb = smem_u32(smem_raw);
    const int tid = threadIdx.x;
    const int lane = tid & 31, wid = tid >> 5;
    const int wm = (wid & 1) * 64;
    const int wn = (wid >> 1) * 32;
    const int m0 = blockIdx.y * GBM;
    const int n0 = blockIdx.x * GBN;

    const int arow = lane & 15;
    const uint32_t ahi = lane >> 4;
    const int brow = (lane & 7) + ((lane >> 4) << 3);
    const uint32_t bhi = (lane >> 3) & 1;

    if (tid == 0) {
        for (int s = 0; s < GSTAGES; s++) {
            MBARRIER_INIT(sb + MB_FULL(s), 1);
            MBARRIER_INIT(sb + MB_EMPTY(s), 8);
        }
        FENCE_PROXY_ASYNC();
    }
    __syncthreads();

    const int KT = K / GBK;

    if (tid == 0) {
        for (int s = 0; s < GSTAGES; s++) {
            MBARRIER_EXPECT_TX(sb + MB_FULL(s), STAGE_BYTES);
            tma2d(sb + SM_A(s), &tma_a, s * GBK, m0, sb + MB_FULL(s));
            tma2d(sb + SM_B(s), &tma_b, s * GBK, n0, sb + MB_FULL(s));
        }
    }

    float acc[4][4][4];
#pragma unroll
    for (int i = 0; i < 4; i++)
#pragma unroll
        for (int j = 0; j < 4; j++)
#pragma unroll
            for (int v = 0; v < 4; v++) acc[i][j][v] = 0.f;

    int st = 0, ph = 0;
    for (int kt = 0; kt < KT; kt++) {
        MBARRIER_WAIT_PARITY(sb + MB_FULL(st), ph);
        const uint32_t sA = sb + SM_A(st);
        const uint32_t sB = sb + SM_B(st);

#pragma unroll
        for (int ks = 0; ks < 4; ks++) {
            uint32_t a[4][4], b[2][4];
#pragma unroll
            for (int mf = 0; mf < 4; mf++) {
                int row = wm + mf * 16 + arow;
                uint32_t addr = sA + row * 128 + ((((uint32_t)ks * 2 + ahi) ^ (row & 7)) << 4);
                LDMATRIX_X4(a[mf][0], a[mf][1], a[mf][2], a[mf][3], addr);
            }
#pragma unroll
            for (int nfp = 0; nfp < 2; nfp++) {
                int row = wn + nfp * 16 + brow;
                uint32_t addr = sB + row * 128 + ((((uint32_t)ks * 2 + bhi) ^ (row & 7)) << 4);
                LDMATRIX_X4(b[nfp][0], b[nfp][1], b[nfp][2], b[nfp][3], addr);
            }
#pragma unroll
            for (int mf = 0; mf < 4; mf++)
#pragma unroll
                for (int nf = 0; nf < 4; nf++)
                    mma_f16(acc[mf][nf], a[mf], &b[nf >> 1][(nf & 1) * 2]);
        }

        if (lane == 0) MBARRIER_ARRIVE(sb + MB_EMPTY(st));
        if (tid == 0 && kt + GSTAGES < KT) {
            MBARRIER_WAIT_PARITY(sb + MB_EMPTY(st), ph);
            MBARRIER_EXPECT_TX(sb + MB_FULL(st), STAGE_BYTES);
            tma2d(sb + SM_A(st), &tma_a, (kt + GSTAGES) * GBK, m0, sb + MB_FULL(st));
            tma2d(sb + SM_B(st), &tma_b, (kt + GSTAGES) * GBK, n0, sb + MB_FULL(st));
        }
        if (++st == GSTAGES) { st = 0; ph ^= 1; }
    }

    const int gID = lane >> 2, tg = lane & 3;
#pragma unroll
    for (int mf = 0; mf < 4; mf++) {
        const int row = m0 + wm + mf * 16 + gID;
#pragma unroll
        for (int nf = 0; nf < 4; nf++) {
            const int col = n0 + wn + nf * 8 + tg * 2;
            if (col < N) {
                *(float2*)&C[(size_t)row * N + col] = make_float2(acc[mf][nf][0], acc[mf][nf][1]);
                *(float2*)&C[(size_t)(row + 8) * N + col] = make_float2(acc[mf][nf][2], acc[mf][nf][3]);
            }
        }
    }
}

// ---------------- fp32 -> fp16 RN conversion ----------------
__global__ void to_half_kernel(const float4* __restrict__ in, uint2* __restrict__ out, int n4)
{
    int i = blockIdx.x * blockDim.x + threadIdx.x;
    if (i < n4) {
        float4 v = in[i];
        __half2 h0 = __floats2half2_rn(v.x, v.y);
        __half2 h1 = __floats2half2_rn(v.z, v.w);
        uint2 r;
        r.x = *reinterpret_cast<uint32_t*>(&h0);
        r.y = *reinterpret_cast<uint32_t*>(&h1);
        out[i] = r;
    }
}

// ---------------- depthwise causal conv (D_CONV=4) + bias + SiLU -> fp16 -----
// 2 channels per thread (vectorized; per-channel math identical to scalar).
__global__ void conv_silu_kernel(const float* __restrict__ convw,
                                 const float* __restrict__ convb)
{
    int idx2 = blockIdx.x * blockDim.x + threadIdx.x;        // pair index
    if (idx2 >= NTOK * DINNER / 2) return;
    int c = (idx2 << 1) & (DINNER - 1);                      // even channel
    int tok = idx2 >> 11;                                    // /(DINNER/2)
    int t = tok & (SEQLEN - 1);
    float2 bias = *(const float2*)&convb[c];
    float y0 = bias.x, y1 = bias.y;
    float2 w0 = *(const float2*)&convw[c * 4];               // convw[c][0..1]
    float2 w1 = *(const float2*)&convw[c * 4 + 2];           // convw[c][2..3]
    float2 w2 = *(const float2*)&convw[(c + 1) * 4];         // convw[c+1][0..1]
    float2 w3 = *(const float2*)&convw[(c + 1) * 4 + 2];     // convw[c+1][2..3]
    float wA[4] = { w0.x, w0.y, w1.x, w1.y };
    float wB[4] = { w2.x, w2.y, w3.x, w3.y };
#pragma unroll
    for (int j = 0; j < 4; j++) {
        int tt = t - 3 + j;
        if (tt >= 0) {
            float2 xv = *(const float2*)&g_xz[(size_t)(tok - 3 + j) * (2 * DINNER) + c];
            y0 = fmaf(wA[j], xv.x, y0);
            y1 = fmaf(wB[j], xv.y, y1);
        }
    }
    float s0 = y0 / (1.f + expf(-y0));
    float s1 = y1 / (1.f + expf(-y1));
    *(__half2*)&g_convh[(size_t)tok * DINNER + c] = __floats2half2_rn(s0, s1);
}

// ---------------- dt projection + softplus; dA = -exp(A_log)*dt --------------
__global__ __launch_bounds__(256) void dt_kernel(const float* __restrict__ dtw,
                                                 const float* __restrict__ dtb,
                                                 const float* __restrict__ A_log)
{
    int sub = threadIdx.x >> 6;
    int h = threadIdx.x & 63;
    int tok = blockIdx.x * 4 + sub;
    __shared__ float raw[4][64];
    raw[sub][h] = g_proj[(size_t)tok * XPROJ + DINNER + h];
    __syncthreads();
    float acc = dtb[h];
#pragma unroll
    for (int k = 0; k < 64; k++) acc = fmaf(dtw[h * 64 + k], raw[sub][k], acc);
    float dt = (acc > 20.f) ? acc : log1pf(expf(acc));
    g_dt[tok * 64 + h] = dt;
    g_dA[tok * 64 + h] = -expf(A_log[h]) * dt;
}

// ============================================================================
// per-chunk local states via split-operand MMA:
// S[p][n] = sum_t Xd[t][p] * B[t][n];  Xd split hi/lo (22-bit effective)
// ============================================================================
#define SST_SBT   0                        // halves
#define SST_SXT   (128 * 72)               // 9216
#define SST_SXTL  (SST_SXT + 64 * 72)      // 13824
#define SST_SA    (SST_SXTL + 64 * 72)     // 18432 halves
#define SST_SMEM  ((SST_SA + 128) * 2)     // bytes

__global__ __launch_bounds__(256) void ssd_states_kernel()
{
    extern __shared__ __align__(16) __half smh[];
    __half* sBT   = smh + SST_SBT;
    __half* sXdT  = smh + SST_SXT;
    __half* sXdTL = smh + SST_SXTL;
    float* sa = (float*)(smh + SST_SA);
    int bid = blockIdx.x;
    int h = bid & 63, c = (bid >> 6) & 63, b = bid >> 12;
    int tok0 = b * SEQLEN + c * CHUNKL;
    int tid = threadIdx.x;
    const int lane = tid & 31, wid = tid >> 5;

    if (tid < 64) sa[tid] = g_dA[(tok0 + tid) * NHEADS + h];
    __syncthreads();
    if (tid == 0) { float s = 0.f; for (int t = 0; t < 64; t++) { s += sa[t]; sa[t] = s; } }
    __syncthreads();
    float alast = sa[63];

    for (int i = tid; i < 8192; i += 256) {
        int t = i >> 7, n = i & 127;
        sBT[n * 72 + t] = __float2half_rn(g_proj[(size_t)(tok0 + t) * XPROJ + (DINNER + NHEADS) + n]);
    }
    for (int i = tid; i < 4096; i += 256) {
        int t = i >> 6, p = i & 63;
        float v = g_proj[(size_t)(tok0 + t) * XPROJ + h * 64 + p]
                * g_dt[(tok0 + t) * NHEADS + h] * expf(alast - sa[t]);
        __half hi, lo; split_h(v, hi, lo);
        sXdT[p * 72 + t] = hi;
        sXdTL[p * 72 + t] = lo;
    }
    __syncthreads();

    const int arow = lane & 15;
    const uint32_t ahx = lane >> 4;
    const int brow = (lane & 7) + ((lane >> 4) << 3);
    const uint32_t bhx = (lane >> 3) & 1;
    const int wm = (wid & 1) * 32;     // p
    const int wn = (wid >> 1) * 32;    // n

    uint32_t xb = smem_u32(sXdT), xlb = smem_u32(sXdTL), bb = smem_u32(sBT);
    float acc[2][4][4];
#pragma unroll
    for (int i = 0; i < 2; i++)
#pragma unroll
        for (int j = 0; j < 4; j++)
#pragma unroll
            for (int v = 0; v < 4; v++) acc[i][j][v] = 0.f;

#pragma unroll
    for (int ks = 0; ks < 4; ks++) {
        uint32_t a[2][4], al[2][4], bfr[2][4];
#pragma unroll
        for (int mf = 0; mf < 2; mf++) {
            int row = wm + mf * 16 + arow;
            LDMATRIX_X4(a[mf][0], a[mf][1], a[mf][2], a[mf][3],
                        xb + row * 144 + ((uint32_t)ks * 2 + ahx) * 16);
            LDMATRIX_X4(al[mf][0], al[mf][1], al[mf][2], al[mf][3],
                        xlb + row * 144 + ((uint32_t)ks * 2 + ahx) * 16);
        }
#pragma unroll
        for (int nfp = 0; nfp < 2; nfp++) {
            int row = wn + nfp * 16 + brow;
            LDMATRIX_X4(bfr[nfp][0], bfr[nfp][1], bfr[nfp][2], bfr[nfp][3],
                        bb + row * 144 + ((uint32_t)ks * 2 + bhx) * 16);
        }
#pragma unroll
        for (int mf = 0; mf < 2; mf++)
#pragma unroll
            for (int nf = 0; nf < 4; nf++) {
                mma_f16(acc[mf][nf], a[mf], &bfr[nf >> 1][(nf & 1) * 2]);
                mma_f16(acc[mf][nf], al[mf], &bfr[nf >> 1][(nf & 1) * 2]);
            }
    }

    const int gID = lane >> 2, tg = lane & 3;
    size_t outbase = ((size_t)((b * 64 + c) * 64 + h)) * 8192;
#pragma unroll
    for (int mf = 0; mf < 2; mf++) {
        int p = wm + mf * 16 + gID;
#pragma unroll
        for (int nf = 0; nf < 4; nf++) {
            int n = wn + nf * 8 + tg * 2;
            *(__half2*)&g_statesh[outbase + (size_t)p * 128 + n] =
                __floats2half2_rn(acc[mf][nf][0], acc[mf][nf][1]);
            *(__half2*)&g_statesh[outbase + (size_t)(p + 8) * 128 + n] =
                __floats2half2_rn(acc[mf][nf][2], acc[mf][nf][3]);
        }
    }
}

// ---------------- inter-chunk sequential scan (fp16 states, fp32 carry) ------
__global__ __launch_bounds__(256) void ssd_scan_kernel()
{
    __shared__ float alast[64];
    int blk = blockIdx.x;
    int slice = blk & 7;
    int bh = blk >> 3;
    int b = bh >> 6, h = bh & 63;
    int tid = threadIdx.x;
    if (tid < 64) {
        int c = tid;
        int tok0 = b * SEQLEN + c * CHUNKL;
        float s = 0.f;
        for (int t = 0; t < 64; t++) s += g_dA[(tok0 + t) * NHEADS + h];
        alast[c] = expf(s);
    }
    __syncthreads();
    float run0 = 0.f, run1 = 0.f, run2 = 0.f, run3 = 0.f;
    int off = slice * 1024 + tid * 4;
    for (int c = 0; c < 64; c++) {
        size_t base = ((size_t)((b * 64 + c) * 64 + h)) * 8192 + off;
        float dec = alast[c];
        uint2 v = *(const uint2*)&g_statesh[base];
        __half2 l0 = *reinterpret_cast<__half2*>(&v.x);
        __half2 l1 = *reinterpret_cast<__half2*>(&v.y);
        float2 f0 = __half22float2(l0);
        float2 f1 = __half22float2(l1);
        __half2 e0 = __floats2half2_rn(run0, run1);
        __half2 e1 = __floats2half2_rn(run2, run3);
        uint2 w;
        w.x = *reinterpret_cast<uint32_t*>(&e0);
        w.y = *reinterpret_cast<uint32_t*>(&e1);
        *(uint2*)&g_statesh[base] = w;
        run0 = fmaf(dec, run0, f0.x);
        run1 = fmaf(dec, run1, f0.y);
        run2 = fmaf(dec, run2, f1.x);
        run3 = fmaf(dec, run3, f1.y);
    }
}

// ============================================================================
// SSD output via split-operand MMA:
//  G = mask * (C @ B^T) * decay   (C split hi/lo; G stored hi/lo)
//  Y = G @ X  +  exp(sa[t]) * (C @ Sin^T)  + X*D, gated by silu(z)
// ============================================================================
#define SO_C    0
#define SO_CLO  (64 * 136)               // 8704
#define SO_B    (2 * 64 * 136)           // 17408
#define SO_SIN  (3 * 64 * 136)           // 26112
#define SO_XT   (4 * 64 * 136)           // 34816
#define SO_G    (SO_XT + 64 * 72)        // 39424
#define SO_GLO  (SO_G + 64 * 72)         // 44032
#define SO_SA   (SO_GLO + 64 * 72)       // 48640 halves
#define SO_SMEM ((SO_SA + 128) * 2)      // 97536 bytes

__global__ __launch_bounds__(256) void ssd_out_kernel(const float* __restrict__ Dp)
{
    extern __shared__ __align__(16) __half smh[];
    __half* sC   = smh + SO_C;
    __half* sCL  = smh + SO_CLO;
    __half* sB   = smh + SO_B;
    __half* sSin = smh + SO_SIN;
    __half* sXT  = smh + SO_XT;
    __half* sG   = smh + SO_G;
    __half* sGL  = smh + SO_GLO;
    float*  sa   = (float*)(smh + SO_SA);

    int bid = blockIdx.x;
    int h = bid & 63, c = (bid >> 6) & 63, b = bid >> 12;
    int tok0 = b * SEQLEN + c * CHUNKL;
    int tid = threadIdx.x;
    const int lane = tid & 31, wid = tid >> 5;

    if (tid < 64) sa[tid] = g_dA[(tok0 + tid) * NHEADS + h];
    __syncthreads();
    if (tid == 0) { float s = 0.f; for (int t = 0; t < 64; t++) { s += sa[t]; sa[t] = s; } }

    size_t sbase = ((size_t)((b * 64 + c) * 64 + h)) * 8192;
    for (int i = tid; i < 8192; i += 256) {
        int t = i >> 7, n = i & 127;
        float cv = g_proj[(size_t)(tok0 + t) * XPROJ + (DINNER + NHEADS + DSTATE) + n];
        __half chi, clo; split_h(cv, chi, clo);
        sC[t * 136 + n]  = chi;
        sCL[t * 136 + n] = clo;
        sB[t * 136 + n]  = __float2half_rn(g_proj[(size_t)(tok0 + t) * XPROJ + (DINNER + NHEADS) + n]);
        sSin[t * 136 + n] = g_statesh[sbase + i];    // t here is p
    }
    for (int i = tid; i < 4096; i += 256) {
        int t = i >> 6, p = i & 63;
        float v = g_proj[(size_t)(tok0 + t) * XPROJ + h * 64 + p] * g_dt[(tok0 + t) * NHEADS + h];
        sXT[p * 72 + t] = __float2half_rn(v);
    }
    __syncthreads();

    const int arow = lane & 15;
    const uint32_t ahx = lane >> 4;
    const int brow = (lane & 7) + ((lane >> 4) << 3);
    const uint32_t bhx = (lane >> 3) & 1;
    const int gID = lane >> 2, tg = lane & 3;

    uint32_t cb = smem_u32(sC), clb = smem_u32(sCL), bb = smem_u32(sB), sinb = smem_u32(sSin);
    uint32_t xtb = smem_u32(sXT), gb = smem_u32(sG), glb = smem_u32(sGL);

    // ---- phase 1: G = (Chi+Clo) @ B^T, masked + decay, store hi/lo fp16 ----
    {
        const int wt = (wid & 3) * 16;     // t
        const int ws = (wid >> 2) * 32;    // s
        float gacc[4][4];
#pragma unroll
        for (int j = 0; j < 4; j++)
#pragma unroll
            for (int v = 0; v < 4; v++) gacc[j][v] = 0.f;

#pragma unroll
        for (int ks = 0; ks < 8; ks++) {
            uint32_t a[4], al[4], bfr[2][4];
            {
                int row = wt + arow;
                LDMATRIX_X4(a[0], a[1], a[2], a[3], cb + row * 272 + ((uint32_t)ks * 2 + ahx) * 16);
                LDMATRIX_X4(al[0], al[1], al[2], al[3], clb + row * 272 + ((uint32_t)ks * 2 + ahx) * 16);
            }
#pragma unroll
            for (int nfp = 0; nfp < 2; nfp++) {
                int row = ws + nfp * 16 + brow;
                LDMATRIX_X4(bfr[nfp][0], bfr[nfp][1], bfr[nfp][2], bfr[nfp][3],
                            bb + row * 272 + ((uint32_t)ks * 2 + bhx) * 16);
            }
#pragma unroll
            for (int nf = 0; nf < 4; nf++) {
                mma_f16(gacc[nf], a, &bfr[nf >> 1][(nf & 1) * 2]);
                mma_f16(gacc[nf], al, &bfr[nf >> 1][(nf & 1) * 2]);
            }
        }

        int t0 = wt + gID, t1 = t0 + 8;
        float e0 = sa[t0], e1 = sa[t1];
#pragma unroll
        for (int nf = 0; nf < 4; nf++) {
            int s0 = ws + nf * 8 + tg * 2;
            float es0 = sa[s0], es1 = sa[s0 + 1];
            float v00 = (s0     <= t0) ? gacc[nf][0] * expf(e0 - es0) : 0.f;
            float v01 = (s0 + 1 <= t0) ? gacc[nf][1] * expf(e0 - es1) : 0.f;
            float v10 = (s0     <= t1) ? gacc[nf][2] * expf(e1 - es0) : 0.f;
            float v11 = (s0 + 1 <= t1) ? gacc[nf][3] * expf(e1 - es1) : 0.f;
            __half h00, l00, h01, l01, h10, l10, h11, l11;
            split_h(v00, h00, l00); split_h(v01, h01, l01);
            split_h(v10, h10, l10); split_h(v11, h11, l11);
            *(__half2*)&sG[t0 * 72 + s0]  = __halves2half2(h00, h01);
            *(__half2*)&sGL[t0 * 72 + s0] = __halves2half2(l00, l01);
            *(__half2*)&sG[t1 * 72 + s0]  = __halves2half2(h10, h11);
            *(__half2*)&sGL[t1 * 72 + s0] = __halves2half2(l10, l11);
        }
    }
    __syncthreads();

    // ---- phase 2: Y = (Ghi+Glo)@X + exp(sa[t]) * ((Chi+Clo)@Sin^T) ----
    {
        const int wt = (wid & 3) * 16;     // t
        const int wp = (wid >> 2) * 32;    // p
        float accd[4][4], acco[4][4];
#pragma unroll
        for (int j = 0; j < 4; j++)
#pragma unroll
            for (int v = 0; v < 4; v++) { accd[j][v] = 0.f; acco[j][v] = 0.f; }

        // diag: A = G[t][s] (k=s,64) split, B = sXT[p][s]
#pragma unroll
        for (int ks = 0; ks < 4; ks++) {
            uint32_t a[4], al[4], bfr[2][4];
            {
                int row = wt + arow;
                LDMATRIX_X4(a[0], a[1], a[2], a[3], gb + row * 144 + ((uint32_t)ks * 2 + ahx) * 16);
                LDMATRIX_X4(al[0], al[1], al[2], al[3], glb + row * 144 + ((uint32_t)ks * 2 + ahx) * 16);
            }
#pragma unroll
            for (int nfp = 0; nfp < 2; nfp++) {
                int row = wp + nfp * 16 + brow;
                LDMATRIX_X4(bfr[nfp][0], bfr[nfp][1], bfr[nfp][2], bfr[nfp][3],
                            xtb + row * 144 + ((uint32_t)ks * 2 + bhx) * 16);
            }
#pragma unroll
            for (int nf = 0; nf < 4; nf++) {
                mma_f16(accd[nf], a, &bfr[nf >> 1][(nf & 1) * 2]);
                mma_f16(accd[nf], al, &bfr[nf >> 1][(nf & 1) * 2]);
            }
        }

        // off: A = C[t][n] (k=n,128) split, B = sSin[p][n]
#pragma unroll
        for (int ks = 0; ks < 8; ks++) {
            uint32_t a[4], al[4], bfr[2][4];
            {
                int row = wt + arow;
                LDMATRIX_X4(a[0], a[1], a[2], a[3], cb + row * 272 + ((uint32_t)ks * 2 + ahx) * 16);
                LDMATRIX_X4(al[0], al[1], al[2], al[3], clb + row * 272 + ((uint32_t)ks * 2 + ahx) * 16);
            }
#pragma unroll
            for (int nfp = 0; nfp < 2; nfp++) {
                int row = wp + nfp * 16 + brow;
                LDMATRIX_X4(bfr[nfp][0], bfr[nfp][1], bfr[nfp][2], bfr[nfp][3],
                            sinb + row * 272 + ((uint32_t)ks * 2 + bhx) * 16);
            }
#pragma unroll
            for (int nf = 0; nf < 4; nf++) {
                mma_f16(acco[nf], a, &bfr[nf >> 1][(nf & 1) * 2]);
                mma_f16(acco[nf], al, &bfr[nf >> 1][(nf & 1) * 2]);
            }
        }

        float dh = Dp[h];
        int t0 = wt + gID;
#pragma unroll
        for (int r = 0; r < 2; r++) {
            int t = t0 + r * 8;
            int tok = tok0 + t;
            float sc = expf(sa[t]);
            const float* projX = &g_proj[(size_t)tok * XPROJ + h * 64];
            const float* zrow = &g_xz[(size_t)tok * (2 * DINNER) + DINNER + h * 64];
            __half* yrow = &g_Yh[(size_t)tok * DINNER + h * 64];
#pragma unroll
            for (int nf = 0; nf < 4; nf++) {
                int p = wp + nf * 8 + tg * 2;
                float y0 = accd[nf][r * 2 + 0] + acco[nf][r * 2 + 0] * sc + projX[p] * dh;
                float y1 = accd[nf][r * 2 + 1] + acco[nf][r * 2 + 1] * sc + projX[p + 1] * dh;
                float z0 = zrow[p], z1 = zrow[p + 1];
                y0 *= z0 / (1.f + expf(-z0));
                y1 *= z1 / (1.f + expf(-z1));
                *(__half2*)&yrow[p] = __floats2half2_rn(y0, y1);
            }
        }
    }
}

// ============================================================================
// host side
// ============================================================================
typedef CUresult (*PFN_encode)(CUtensorMap*, CUtensorMapDataType, cuuint32_t, void*,
    const cuuint64_t*, const cuuint64_t*, const cuuint32_t*, const cuuint32_t*,
    CUtensorMapInterleave, CUtensorMapSwizzle, CUtensorMapL2promotion, CUtensorMapFloatOOBfill);

static PFN_encode get_encoder() {
    void* p = nullptr;
    cudaDriverEntryPointQueryResult qr;
#if CUDART_VERSION >= 12050
    cudaGetDriverEntryPointByVersion("cuTensorMapEncodeTiled", &p, 12000, cudaEnableDefault, &qr);
#else
    cudaGetDriverEntryPoint("cuTensorMapEncodeTiled", &p, cudaEnableDefault, &qr);
#endif
    return (PFN_encode)p;
}

static void make_map_h(PFN_encode enc, CUtensorMap* m, const void* ptr,
                       uint64_t d0, uint64_t d1, uint32_t b0, uint32_t b1)
{
    cuuint64_t dims[2] = { d0, d1 };
    cuuint64_t strides[1] = { d0 * 2 };
    cuuint32_t box[2] = { b0, b1 };
    cuuint32_t es[2] = { 1, 1 };
    enc(m, CU_TENSOR_MAP_DATA_TYPE_FLOAT16, 2, (void*)ptr, dims, strides, box, es,
        CU_TENSOR_MAP_INTERLEAVE_NONE, CU_TENSOR_MAP_SWIZZLE_128B,
        CU_TENSOR_MAP_L2_PROMOTION_L2_128B, CU_TENSOR_MAP_FLOAT_OOB_FILL_NONE);
}

extern "C" void kernel_launch(void* const* d_in, const int* in_sizes, int n_in,
                              void* d_out, int out_size)
{
    const float* x          = (const float*)d_in[0];
    const float* conv_w     = (const float*)d_in[2];
    const float* conv_b     = (const float*)d_in[3];
    const float* dt_proj_w  = (const float*)d_in[5];
    const float* dt_proj_b  = (const float*)d_in[6];
    const float* A_log      = (const float*)d_in[7];
    const float* Dp         = (const float*)d_in[8];
    float* out = (float*)d_out;

    void *p_xh, *p_wih, *p_wxh, *p_woh, *p_convh, *p_Yh;
    float *p_xz, *p_proj;
    cudaGetSymbolAddress(&p_xh,    g_xh);
    cudaGetSymbolAddress(&p_wih,   g_wih);
    cudaGetSymbolAddress(&p_wxh,   g_wxh);
    cudaGetSymbolAddress(&p_woh,   g_woh);
    cudaGetSymbolAddress(&p_convh, g_convh);
    cudaGetSymbolAddress(&p_Yh,    g_Yh);
    cudaGetSymbolAddress((void**)&p_xz,   g_xz);
    cudaGetSymbolAddress((void**)&p_proj, g_proj);

    cudaFuncSetAttribute(gemm_f16_mma,      cudaFuncAttributeMaxDynamicSharedMemorySize, GEMM_SMEM);
    cudaFuncSetAttribute(ssd_states_kernel, cudaFuncAttributeMaxDynamicSharedMemorySize, SST_SMEM);
    cudaFuncSetAttribute(ssd_out_kernel,    cudaFuncAttributeMaxDynamicSharedMemorySize, SO_SMEM);

    PFN_encode enc = get_encoder();
    CUtensorMap mA1, mB1, mA2, mB2, mA3, mB3;
    make_map_h(enc, &mA1, p_xh,    DMODEL, NTOK,       GBK, GBM);
    make_map_h(enc, &mB1, p_wih,   DMODEL, 2 * DINNER, GBK, GBN);
    make_map_h(enc, &mA2, p_convh, DINNER, NTOK,       GBK, GBM);
    make_map_h(enc, &mB2, p_wxh,   DINNER, XPROJ,      GBK, GBN);
    make_map_h(enc, &mA3, p_Yh,    DINNER, NTOK,       GBK, GBM);
    make_map_h(enc, &mB3, p_woh,   DINNER, DMODEL,     GBK, GBN);

    to_half_kernel<<<(NTOK * DMODEL / 4 + 255) / 256, 256>>>((const float4*)x, (uint2*)p_xh, NTOK * DMODEL / 4);
    to_half_kernel<<<(2 * DINNER * DMODEL / 4 + 255) / 256, 256>>>((const float4*)d_in[1], (uint2*)p_wih, 2 * DINNER * DMODEL / 4);
    to_half_kernel<<<((int)((size_t)XPROJ * DINNER / 4) + 255) / 256, 256>>>((const float4*)d_in[4], (uint2*)p_wxh, (int)((size_t)XPROJ * DINNER / 4));
    to_half_kernel<<<(DMODEL * DINNER / 4 + 255) / 256, 256>>>((const float4*)d_in[9], (uint2*)p_woh, DMODEL * DINNER / 4);

    // 1) xz = x @ in_proj_w^T  (fp32 out — dt path amplifies rounding via exp(cumsum))
    gemm_f16_mma<<<dim3(2 * DINNER / GBN, NTOK / GBM), 256, GEMM_SMEM>>>(mA1, mB1, p_xz, 2 * DINNER, DMODEL);
    // 2) depthwise conv + bias + silu (fp16 out, 2 ch/thread)
    conv_silu_kernel<<<(NTOK * DINNER / 2) / 256, 256>>>(conv_w, conv_b);
    // 3) proj = conv @ x_proj_w^T (fp32 out)
    gemm_f16_mma<<<dim3((XPROJ + GBN - 1) / GBN, NTOK / GBM), 256, GEMM_SMEM>>>(mA2, mB2, p_proj, XPROJ, DINNER);
    // 4) dt
    dt_kernel<<<NTOK / 4, 256>>>(dt_proj_w, dt_proj_b, A_log);
    // 5) per-chunk local states (split MMA, fp16 states out)
    ssd_states_kernel<<<BATCH * NCHUNK * NHEADS, 256, SST_SMEM>>>();
    // 6) inter-chunk scan (fp16 states, fp32 carry)
    ssd_scan_kernel<<<BATCH * NHEADS * 8, 256>>>();
    // 7) SSD output + gating (split MMA, fp16 out)
    ssd_out_kernel<<<BATCH * NCHUNK * NHEADS, 256, SO_SMEM>>>(Dp);
    // 8) out = Y @ out_proj_w^T (fp32 out)
    gemm_f16_mma<<<dim3(DMODEL / GBN, NTOK / GBM), 256, GEMM_SMEM>>>(mA3, mB3, out, DMODEL, DINNER);
}

// round 16
// speedup vs baseline: 1.0012x; 1.0010x over previous
#include <cuda_runtime.h>
#include <cuda.h>
#include <cuda_fp16.h>
#include <math.h>
#include <stdint.h>

// ---------------- problem constants ----------------
#define BATCH   2
#define SEQLEN  4096
#define DMODEL  2048
#define DINNER  4096
#define NHEADS  64
#define HEADDIM 64
#define DSTATE  128
#define CHUNKL  64
#define NCHUNK  64
#define XPROJ   4416
#define NTOK    (BATCH*SEQLEN)   // 8192

// ---------------- scratch (device globals; no allocs allowed) ----------------
__device__ float g_xz[(size_t)NTOK * 2 * DINNER];     // fp32 (x_branch | z_branch)
__device__ float g_proj[(size_t)NTOK * XPROJ];
__device__ float g_dt[NTOK * NHEADS];
__device__ float g_dA[NTOK * NHEADS];
__device__ __half g_statesh[(size_t)BATCH * NCHUNK * NHEADS * HEADDIM * DSTATE];
// fp16 GEMM inputs
__device__ __half g_xh[(size_t)NTOK * DMODEL];
__device__ __half g_wih[(size_t)2 * DINNER * DMODEL];
__device__ __half g_wxh[(size_t)XPROJ * DINNER];
__device__ __half g_woh[(size_t)DMODEL * DINNER];
__device__ __half g_convh[(size_t)NTOK * DINNER];
__device__ __half g_Yh[(size_t)NTOK * DINNER];

// ============================================================================
// PTX helpers (baseline sm_80/sm_90 features only)
// ============================================================================
__device__ __forceinline__ uint32_t smem_u32(const void* p) {
    uint32_t a;
    asm("{ .reg .u64 t; cvta.to.shared.u64 t, %1; cvt.u32.u64 %0, t; }" : "=r"(a) : "l"(p));
    return a;
}

#define MBARRIER_INIT(addr, cnt) \
    asm volatile("mbarrier.init.shared.b64 [%0], %1;" :: "r"((uint32_t)(addr)), "r"((uint32_t)(cnt)) : "memory")

#define MBARRIER_EXPECT_TX(addr, bytes) \
    asm volatile("mbarrier.arrive.expect_tx.shared.b64 _, [%0], %1;" :: "r"((uint32_t)(addr)), "r"((uint32_t)(bytes)) : "memory")

#define MBARRIER_ARRIVE(addr) \
    asm volatile("mbarrier.arrive.shared.b64 _, [%0];" :: "r"((uint32_t)(addr)) : "memory")

#define MBARRIER_WAIT_PARITY(addr, parity) do {                                    \
    uint32_t _m = (uint32_t)(addr); uint32_t _p = (uint32_t)(parity); uint32_t _d; \
    asm volatile("{\n\t.reg .pred p;\n\t"                                          \
        "mbarrier.try_wait.parity.acquire.cta.shared::cta.b64 p, [%1], %2;\n\t"    \
        "selp.b32 %0, 1, 0, p;\n\t}"                                               \
        : "=r"(_d) : "r"(_m), "r"(_p) : "memory");                                 \
    if (!_d) {                                                                     \
        asm volatile("{\n\t.reg .pred P1;\n\t"                                     \
            "WL_%=:\n\t"                                                           \
            "mbarrier.try_wait.parity.acquire.cta.shared::cta.b64 P1, [%0], %1, 0x989680;\n\t" \
            "@P1 bra.uni WD_%=;\n\t"                                               \
            "bra.uni WL_%=;\n\t"                                                   \
            "WD_%=:\n\t}"                                                          \
            :: "r"(_m), "r"(_p) : "memory");                                       \
    }                                                                              \
} while (0)

#define FENCE_PROXY_ASYNC()   asm volatile("fence.proxy.async;" ::: "memory")

__device__ __forceinline__ void tma2d(uint32_t smem, const CUtensorMap* map,
                                      int cx, int cy, uint32_t mbar) {
    asm volatile(
        "cp.async.bulk.tensor.2d.shared::cta.global.tile.mbarrier::complete_tx::bytes "
        "[%0], [%1, {%2, %3}], [%4];"
        :: "r"(smem), "l"(map), "r"(cx), "r"(cy), "r"(mbar) : "memory");
}

#define LDMATRIX_X4(r0, r1, r2, r3, addr) \
    asm volatile("ldmatrix.sync.aligned.m8n8.x4.shared.b16 {%0,%1,%2,%3}, [%4];" \
        : "=r"(r0), "=r"(r1), "=r"(r2), "=r"(r3) : "r"(addr))

// mma m16n8k16 fp16 in, fp32 accum (sm_80+ baseline)
__device__ __forceinline__ void mma_f16(float* d, const uint32_t* a, const uint32_t* b) {
    asm volatile(
        "mma.sync.aligned.m16n8k16.row.col.f32.f16.f16.f32 "
        "{%0,%1,%2,%3}, {%4,%5,%6,%7}, {%8,%9}, {%0,%1,%2,%3};"
        : "+f"(d[0]), "+f"(d[1]), "+f"(d[2]), "+f"(d[3])
        : "r"(a[0]), "r"(a[1]), "r"(a[2]), "r"(a[3]), "r"(b[0]), "r"(b[1]));
}

__device__ __forceinline__ void split_h(float v, __half& hi, __half& lo) {
    hi = __float2half_rn(v);
    lo = __float2half_rn(v - __half2float(hi));
}

// ============================================================================
// fp16 HMMA GEMM: C[m,n] = sum_k A[m,k]*W[n,k]  (A,W fp16; C fp32)
// CTA tile 128x128, BK=64, 3-stage TMA pipeline (R7-proven refill structure:
// refill strictly AFTER the stage's own drain is confirmed — race-free).
// ============================================================================
#define GSTAGES 3
#define GBM 128
#define GBN 128
#define GBK 64
#define STAGE_BYTES  32768
#define SM_A(s)  ((s) * STAGE_BYTES)
#define SM_B(s)  ((s) * STAGE_BYTES + 16384)
#define MB_BASE  (GSTAGES * STAGE_BYTES)
#define MB_FULL(s)  (MB_BASE + 8 * (s))
#define MB_EMPTY(s) (MB_BASE + 32 + 8 * (s))
#define GEMM_SMEM   (MB_BASE + 128)

__global__ __launch_bounds__(256, 2) void gemm_f16_mma(
    const __grid_constant__ CUtensorMap tma_a,
    const __grid_constant__ CUtensorMap tma_b,
    float* __restrict__ C, int N, int K)
{
    extern __shared__ __align__(1024) char smem_raw[];
    uint32_t sb = smem_u32(smem_raw);
    const int tid = threadIdx.x;
    const int lane = tid & 31, wid = tid >> 5;
    const int wm = (wid & 1) * 64;
    const int wn = (wid >> 1) * 32;
    const int m0 = blockIdx.y * GBM;
    const int n0 = blockIdx.x * GBN;

    const int arow = lane & 15;
    const uint32_t ahi = lane >> 4;
    const int brow = (lane & 7) + ((lane >> 4) << 3);
    const uint32_t bhi = (lane >> 3) & 1;

    if (tid == 0) {
        for (int s = 0; s < GSTAGES; s++) {
            MBARRIER_INIT(sb + MB_FULL(s), 1);
            MBARRIER_INIT(sb + MB_EMPTY(s), 8);
        }
        FENCE_PROXY_ASYNC();
    }
    __syncthreads();

    const int KT = K / GBK;

    if (tid == 0) {
        for (int s = 0; s < GSTAGES; s++) {
            MBARRIER_EXPECT_TX(sb + MB_FULL(s), STAGE_BYTES);
            tma2d(sb + SM_A(s), &tma_a, s * GBK, m0, sb + MB_FULL(s));
            tma2d(sb + SM_B(s), &tma_b, s * GBK, n0, sb + MB_FULL(s));
        }
    }

    float acc[4][4][4];
#pragma unroll
    for (int i = 0; i < 4; i++)
#pragma unroll
        for (int j = 0; j < 4; j++)
#pragma unroll
            for (int v = 0; v < 4; v++) acc[i][j][v] = 0.f;

    int st = 0, ph = 0;
    for (int kt = 0; kt < KT; kt++) {
        MBARRIER_WAIT_PARITY(sb + MB_FULL(st), ph);
        const uint32_t sA = sb + SM_A(st);
        const uint32_t sB = sb + SM_B(st);

#pragma unroll
        for (int ks = 0; ks < 4; ks++) {
            uint32_t a[4][4], b[2][4];
#pragma unroll
            for (int mf = 0; mf < 4; mf++) {
                int row = wm + mf * 16 + arow;
                uint32_t addr = sA + row * 128 + ((((uint32_t)ks * 2 + ahi) ^ (row & 7)) << 4);
                LDMATRIX_X4(a[mf][0], a[mf][1], a[mf][2], a[mf][3], addr);
            }
#pragma unroll
            for (int nfp = 0; nfp < 2; nfp++) {
                int row = wn + nfp * 16 + brow;
                uint32_t addr = sB + row * 128 + ((((uint32_t)ks * 2 + bhi) ^ (row & 7)) << 4);
                LDMATRIX_X4(b[nfp][0], b[nfp][1], b[nfp][2], b[nfp][3], addr);
            }
#pragma unroll
            for (int mf = 0; mf < 4; mf++)
#pragma unroll
                for (int nf = 0; nf < 4; nf++)
                    mma_f16(acc[mf][nf], a[mf], &b[nf >> 1][(nf & 1) * 2]);
        }

        if (lane == 0) MBARRIER_ARRIVE(sb + MB_EMPTY(st));
        if (tid == 0 && kt + GSTAGES < KT) {
            MBARRIER_WAIT_PARITY(sb + MB_EMPTY(st), ph);
            MBARRIER_EXPECT_TX(sb + MB_FULL(st), STAGE_BYTES);
            tma2d(sb + SM_A(st), &tma_a, (kt + GSTAGES) * GBK, m0, sb + MB_FULL(st));
            tma2d(sb + SM_B(st), &tma_b, (kt + GSTAGES) * GBK, n0, sb + MB_FULL(st));
        }
        if (++st == GSTAGES) { st = 0; ph ^= 1; }
    }

    const int gID = lane >> 2, tg = lane & 3;
#pragma unroll
    for (int mf = 0; mf < 4; mf++) {
        const int row = m0 + wm + mf * 16 + gID;
#pragma unroll
        for (int nf = 0; nf < 4; nf++) {
            const int col = n0 + wn + nf * 8 + tg * 2;
            if (col < N) {
                *(float2*)&C[(size_t)row * N + col] = make_float2(acc[mf][nf][0], acc[mf][nf][1]);
                *(float2*)&C[(size_t)(row + 8) * N + col] = make_float2(acc[mf][nf][2], acc[mf][nf][3]);
            }
        }
    }
}

// ---------------- fp32 -> fp16 RN conversion ----------------
__global__ void to_half_kernel(const float4* __restrict__ in, uint2* __restrict__ out, int n4)
{
    int i = blockIdx.x * blockDim.x + threadIdx.x;
    if (i < n4) {
        float4 v = in[i];
        __half2 h0 = __floats2half2_rn(v.x, v.y);
        __half2 h1 = __floats2half2_rn(v.z, v.w);
        uint2 r;
        r.x = *reinterpret_cast<uint32_t*>(&h0);
        r.y = *reinterpret_cast<uint32_t*>(&h1);
        out[i] = r;
    }
}

// ---------------- depthwise causal conv (D_CONV=4) + bias + SiLU -> fp16 -----
// 2 channels per thread (vectorized; per-channel math identical to scalar).
__global__ void conv_silu_kernel(const float* __restrict__ convw,
                                 const float* __restrict__ convb)
{
    int idx2 = blockIdx.x * blockDim.x + threadIdx.x;        // pair index
    if (idx2 >= NTOK * DINNER / 2) return;
    int c = (idx2 << 1) & (DINNER - 1);                      // even channel
    int tok = idx2 >> 11;                                    // /(DINNER/2)
    int t = tok & (SEQLEN - 1);
    float2 bias = *(const float2*)&convb[c];
    float y0 = bias.x, y1 = bias.y;
    float2 w0 = *(const float2*)&convw[c * 4];               // convw[c][0..1]
    float2 w1 = *(const float2*)&convw[c * 4 + 2];           // convw[c][2..3]
    float2 w2 = *(const float2*)&convw[(c + 1) * 4];         // convw[c+1][0..1]
    float2 w3 = *(const float2*)&convw[(c + 1) * 4 + 2];     // convw[c+1][2..3]
    float wA[4] = { w0.x, w0.y, w1.x, w1.y };
    float wB[4] = { w2.x, w2.y, w3.x, w3.y };
#pragma unroll
    for (int j = 0; j < 4; j++) {
        int tt = t - 3 + j;
        if (tt >= 0) {
            float2 xv = *(const float2*)&g_xz[(size_t)(tok - 3 + j) * (2 * DINNER) + c];
            y0 = fmaf(wA[j], xv.x, y0);
            y1 = fmaf(wB[j], xv.y, y1);
        }
    }
    float s0 = y0 / (1.f + expf(-y0));
    float s1 = y1 / (1.f + expf(-y1));
    *(__half2*)&g_convh[(size_t)tok * DINNER + c] = __floats2half2_rn(s0, s1);
}

// ---------------- dt projection + softplus; dA = -exp(A_log)*dt --------------
__global__ __launch_bounds__(256) void dt_kernel(const float* __restrict__ dtw,
                                                 const float* __restrict__ dtb,
                                                 const float* __restrict__ A_log)
{
    int sub = threadIdx.x >> 6;
    int h = threadIdx.x & 63;
    int tok = blockIdx.x * 4 + sub;
    __shared__ float raw[4][64];
    raw[sub][h] = g_proj[(size_t)tok * XPROJ + DINNER + h];
    __syncthreads();
    float acc = dtb[h];
#pragma unroll
    for (int k = 0; k < 64; k++) acc = fmaf(dtw[h * 64 + k], raw[sub][k], acc);
    float dt = (acc > 20.f) ? acc : log1pf(expf(acc));
    g_dt[tok * 64 + h] = dt;
    g_dA[tok * 64 + h] = -expf(A_log[h]) * dt;
}

// ============================================================================
// per-chunk local states via split-operand MMA:
// S[p][n] = sum_t Xd[t][p] * B[t][n];  Xd split hi/lo (22-bit effective)
// ============================================================================
#define SST_SBT   0                        // halves
#define SST_SXT   (128 * 72)               // 9216
#define SST_SXTL  (SST_SXT + 64 * 72)      // 13824
#define SST_SA    (SST_SXTL + 64 * 72)     // 18432 halves
#define SST_SMEM  ((SST_SA + 128) * 2)     // bytes

__global__ __launch_bounds__(256) void ssd_states_kernel()
{
    extern __shared__ __align__(16) __half smh[];
    __half* sBT   = smh + SST_SBT;
    __half* sXdT  = smh + SST_SXT;
    __half* sXdTL = smh + SST_SXTL;
    float* sa = (float*)(smh + SST_SA);
    int bid = blockIdx.x;
    int h = bid & 63, c = (bid >> 6) & 63, b = bid >> 12;
    int tok0 = b * SEQLEN + c * CHUNKL;
    int tid = threadIdx.x;
    const int lane = tid & 31, wid = tid >> 5;

    if (tid < 64) sa[tid] = g_dA[(tok0 + tid) * NHEADS + h];
    __syncthreads();
    if (tid == 0) { float s = 0.f; for (int t = 0; t < 64; t++) { s += sa[t]; sa[t] = s; } }
    __syncthreads();
    float alast = sa[63];

    for (int i = tid; i < 8192; i += 256) {
        int t = i >> 7, n = i & 127;
        sBT[n * 72 + t] = __float2half_rn(g_proj[(size_t)(tok0 + t) * XPROJ + (DINNER + NHEADS) + n]);
    }
    for (int i = tid; i < 4096; i += 256) {
        int t = i >> 6, p = i & 63;
        float v = g_proj[(size_t)(tok0 + t) * XPROJ + h * 64 + p]
                * g_dt[(tok0 + t) * NHEADS + h] * expf(alast - sa[t]);
        __half hi, lo; split_h(v, hi, lo);
        sXdT[p * 72 + t] = hi;
        sXdTL[p * 72 + t] = lo;
    }
    __syncthreads();

    const int arow = lane & 15;
    const uint32_t ahx = lane >> 4;
    const int brow = (lane & 7) + ((lane >> 4) << 3);
    const uint32_t bhx = (lane >> 3) & 1;
    const int wm = (wid & 1) * 32;     // p
    const int wn = (wid >> 1) * 32;    // n

    uint32_t xb = smem_u32(sXdT), xlb = smem_u32(sXdTL), bb = smem_u32(sBT);
    float acc[2][4][4];
#pragma unroll
    for (int i = 0; i < 2; i++)
#pragma unroll
        for (int j = 0; j < 4; j++)
#pragma unroll
            for (int v = 0; v < 4; v++) acc[i][j][v] = 0.f;

#pragma unroll
    for (int ks = 0; ks < 4; ks++) {
        uint32_t a[2][4], al[2][4], bfr[2][4];
#pragma unroll
        for (int mf = 0; mf < 2; mf++) {
            int row = wm + mf * 16 + arow;
            LDMATRIX_X4(a[mf][0], a[mf][1], a[mf][2], a[mf][3],
                        xb + row * 144 + ((uint32_t)ks * 2 + ahx) * 16);
            LDMATRIX_X4(al[mf][0], al[mf][1], al[mf][2], al[mf][3],
                        xlb + row * 144 + ((uint32_t)ks * 2 + ahx) * 16);
        }
#pragma unroll
        for (int nfp = 0; nfp < 2; nfp++) {
            int row = wn + nfp * 16 + brow;
            LDMATRIX_X4(bfr[nfp][0], bfr[nfp][1], bfr[nfp][2], bfr[nfp][3],
                        bb + row * 144 + ((uint32_t)ks * 2 + bhx) * 16);
        }
#pragma unroll
        for (int mf = 0; mf < 2; mf++)
#pragma unroll
            for (int nf = 0; nf < 4; nf++) {
                mma_f16(acc[mf][nf], a[mf], &bfr[nf >> 1][(nf & 1) * 2]);
                mma_f16(acc[mf][nf], al[mf], &bfr[nf >> 1][(nf & 1) * 2]);
            }
    }

    const int gID = lane >> 2, tg = lane & 3;
    size_t outbase = ((size_t)((b * 64 + c) * 64 + h)) * 8192;
#pragma unroll
    for (int mf = 0; mf < 2; mf++) {
        int p = wm + mf * 16 + gID;
#pragma unroll
        for (int nf = 0; nf < 4; nf++) {
            int n = wn + nf * 8 + tg * 2;
            *(__half2*)&g_statesh[outbase + (size_t)p * 128 + n] =
                __floats2half2_rn(acc[mf][nf][0], acc[mf][nf][1]);
            *(__half2*)&g_statesh[outbase + (size_t)(p + 8) * 128 + n] =
                __floats2half2_rn(acc[mf][nf][2], acc[mf][nf][3]);
        }
    }
}

// ---------------- inter-chunk sequential scan (fp16 states, fp32 carry) ------
__global__ __launch_bounds__(256) void ssd_scan_kernel()
{
    __shared__ float alast[64];
    int blk = blockIdx.x;
    int slice = blk & 7;
    int bh = blk >> 3;
    int b = bh >> 6, h = bh & 63;
    int tid = threadIdx.x;
    if (tid < 64) {
        int c = tid;
        int tok0 = b * SEQLEN + c * CHUNKL;
        float s = 0.f;
        for (int t = 0; t < 64; t++) s += g_dA[(tok0 + t) * NHEADS + h];
        alast[c] = expf(s);
    }
    __syncthreads();
    float run0 = 0.f, run1 = 0.f, run2 = 0.f, run3 = 0.f;
    int off = slice * 1024 + tid * 4;
    for (int c = 0; c < 64; c++) {
        size_t base = ((size_t)((b * 64 + c) * 64 + h)) * 8192 + off;
        float dec = alast[c];
        uint2 v = *(const uint2*)&g_statesh[base];
        __half2 l0 = *reinterpret_cast<__half2*>(&v.x);
        __half2 l1 = *reinterpret_cast<__half2*>(&v.y);
        float2 f0 = __half22float2(l0);
        float2 f1 = __half22float2(l1);
        __half2 e0 = __floats2half2_rn(run0, run1);
        __half2 e1 = __floats2half2_rn(run2, run3);
        uint2 w;
        w.x = *reinterpret_cast<uint32_t*>(&e0);
        w.y = *reinterpret_cast<uint32_t*>(&e1);
        *(uint2*)&g_statesh[base] = w;
        run0 = fmaf(dec, run0, f0.x);
        run1 = fmaf(dec, run1, f0.y);
        run2 = fmaf(dec, run2, f1.x);
        run3 = fmaf(dec, run3, f1.y);
    }
}

// ============================================================================
// SSD output via split-operand MMA:
//  G = mask * (C @ B^T) * decay   (C split hi/lo; G stored hi/lo)
//  Y = G @ X  +  exp(sa[t]) * (C @ Sin^T)  + X*D, gated by silu(z)
// ============================================================================
#define SO_C    0
#define SO_CLO  (64 * 136)               // 8704
#define SO_B    (2 * 64 * 136)           // 17408
#define SO_SIN  (3 * 64 * 136)           // 26112
#define SO_XT   (4 * 64 * 136)           // 34816
#define SO_G    (SO_XT + 64 * 72)        // 39424
#define SO_GLO  (SO_G + 64 * 72)         // 44032
#define SO_SA   (SO_GLO + 64 * 72)       // 48640 halves
#define SO_SMEM ((SO_SA + 128) * 2)      // 97536 bytes

__global__ __launch_bounds__(256) void ssd_out_kernel(const float* __restrict__ Dp)
{
    extern __shared__ __align__(16) __half smh[];
    __half* sC   = smh + SO_C;
    __half* sCL  = smh + SO_CLO;
    __half* sB   = smh + SO_B;
    __half* sSin = smh + SO_SIN;
    __half* sXT  = smh + SO_XT;
    __half* sG   = smh + SO_G;
    __half* sGL  = smh + SO_GLO;
    float*  sa   = (float*)(smh + SO_SA);

    int bid = blockIdx.x;
    int h = bid & 63, c = (bid >> 6) & 63, b = bid >> 12;
    int tok0 = b * SEQLEN + c * CHUNKL;
    int tid = threadIdx.x;
    const int lane = tid & 31, wid = tid >> 5;

    if (tid < 64) sa[tid] = g_dA[(tok0 + tid) * NHEADS + h];
    __syncthreads();
    if (tid == 0) { float s = 0.f; for (int t = 0; t < 64; t++) { s += sa[t]; sa[t] = s; } }

    size_t sbase = ((size_t)((b * 64 + c) * 64 + h)) * 8192;
    for (int i = tid; i < 8192; i += 256) {
        int t = i >> 7, n = i & 127;
        float cv = g_proj[(size_t)(tok0 + t) * XPROJ + (DINNER + NHEADS + DSTATE) + n];
        __half chi, clo; split_h(cv, chi, clo);
        sC[t * 136 + n]  = chi;
        sCL[t * 136 + n] = clo;
        sB[t * 136 + n]  = __float2half_rn(g_proj[(size_t)(tok0 + t) * XPROJ + (DINNER + NHEADS) + n]);
        sSin[t * 136 + n] = g_statesh[sbase + i];    // t here is p
    }
    for (int i = tid; i < 4096; i += 256) {
        int t = i >> 6, p = i & 63;
        float v = g_proj[(size_t)(tok0 + t) * XPROJ + h * 64 + p] * g_dt[(tok0 + t) * NHEADS + h];
        sXT[p * 72 + t] = __float2half_rn(v);
    }
    __syncthreads();

    const int arow = lane & 15;
    const uint32_t ahx = lane >> 4;
    const int brow = (lane & 7) + ((lane >> 4) << 3);
    const uint32_t bhx = (lane >> 3) & 1;
    const int gID = lane >> 2, tg = lane & 3;

    uint32_t cb = smem_u32(sC), clb = smem_u32(sCL), bb = smem_u32(sB), sinb = smem_u32(sSin);
    uint32_t xtb = smem_u32(sXT), gb = smem_u32(sG), glb = smem_u32(sGL);

    // ---- phase 1: G = (Chi+Clo) @ B^T, masked + decay, store hi/lo fp16 ----
    {
        const int wt = (wid & 3) * 16;     // t
        const int ws = (wid >> 2) * 32;    // s
        float gacc[4][4];
#pragma unroll
        for (int j = 0; j < 4; j++)
#pragma unroll
            for (int v = 0; v < 4; v++) gacc[j][v] = 0.f;

#pragma unroll
        for (int ks = 0; ks < 8; ks++) {
            uint32_t a[4], al[4], bfr[2][4];
            {
                int row = wt + arow;
                LDMATRIX_X4(a[0], a[1], a[2], a[3], cb + row * 272 + ((uint32_t)ks * 2 + ahx) * 16);
                LDMATRIX_X4(al[0], al[1], al[2], al[3], clb + row * 272 + ((uint32_t)ks * 2 + ahx) * 16);
            }
#pragma unroll
            for (int nfp = 0; nfp < 2; nfp++) {
                int row = ws + nfp * 16 + brow;
                LDMATRIX_X4(bfr[nfp][0], bfr[nfp][1], bfr[nfp][2], bfr[nfp][3],
                            bb + row * 272 + ((uint32_t)ks * 2 + bhx) * 16);
            }
#pragma unroll
            for (int nf = 0; nf < 4; nf++) {
                mma_f16(gacc[nf], a, &bfr[nf >> 1][(nf & 1) * 2]);
                mma_f16(gacc[nf], al, &bfr[nf >> 1][(nf & 1) * 2]);
            }
        }

        int t0 = wt + gID, t1 = t0 + 8;
        float e0 = sa[t0], e1 = sa[t1];
#pragma unroll
        for (int nf = 0; nf < 4; nf++) {
            int s0 = ws + nf * 8 + tg * 2;
            float es0 = sa[s0], es1 = sa[s0 + 1];
            float v00 = (s0     <= t0) ? gacc[nf][0] * expf(e0 - es0) : 0.f;
            float v01 = (s0 + 1 <= t0) ? gacc[nf][1] * expf(e0 - es1) : 0.f;
            float v10 = (s0     <= t1) ? gacc[nf][2] * expf(e1 - es0) : 0.f;
            float v11 = (s0 + 1 <= t1) ? gacc[nf][3] * expf(e1 - es1) : 0.f;
            __half h00, l00, h01, l01, h10, l10, h11, l11;
            split_h(v00, h00, l00); split_h(v01, h01, l01);
            split_h(v10, h10, l10); split_h(v11, h11, l11);
            *(__half2*)&sG[t0 * 72 + s0]  = __halves2half2(h00, h01);
            *(__half2*)&sGL[t0 * 72 + s0] = __halves2half2(l00, l01);
            *(__half2*)&sG[t1 * 72 + s0]  = __halves2half2(h10, h11);
            *(__half2*)&sGL[t1 * 72 + s0] = __halves2half2(l10, l11);
        }
    }
    __syncthreads();

    // ---- phase 2: Y = (Ghi+Glo)@X + exp(sa[t]) * ((Chi+Clo)@Sin^T) ----
    {
        const int wt = (wid & 3) * 16;     // t
        const int wp = (wid >> 2) * 32;    // p
        float accd[4][4], acco[4][4];
#pragma unroll
        for (int j = 0; j < 4; j++)
#pragma unroll
            for (int v = 0; v < 4; v++) { accd[j][v] = 0.f; acco[j][v] = 0.f; }

        // diag: A = G[t][s] (k=s,64) split, B = sXT[p][s]
#pragma unroll
        for (int ks = 0; ks < 4; ks++) {
            uint32_t a[4], al[4], bfr[2][4];
            {
                int row = wt + arow;
                LDMATRIX_X4(a[0], a[1], a[2], a[3], gb + row * 144 + ((uint32_t)ks * 2 + ahx) * 16);
                LDMATRIX_X4(al[0], al[1], al[2], al[3], glb + row * 144 + ((uint32_t)ks * 2 + ahx) * 16);
            }
#pragma unroll
            for (int nfp = 0; nfp < 2; nfp++) {
                int row = wp + nfp * 16 + brow;
                LDMATRIX_X4(bfr[nfp][0], bfr[nfp][1], bfr[nfp][2], bfr[nfp][3],
                            xtb + row * 144 + ((uint32_t)ks * 2 + bhx) * 16);
            }
#pragma unroll
            for (int nf = 0; nf < 4; nf++) {
                mma_f16(accd[nf], a, &bfr[nf >> 1][(nf & 1) * 2]);
                mma_f16(accd[nf], al, &bfr[nf >> 1][(nf & 1) * 2]);
            }
        }

        // off: A = C[t][n] (k=n,128) split, B = sSin[p][n]
#pragma unroll
        for (int ks = 0; ks < 8; ks++) {
            uint32_t a[4], al[4], bfr[2][4];
            {
                int row = wt + arow;
                LDMATRIX_X4(a[0], a[1], a[2], a[3], cb + row * 272 + ((uint32_t)ks * 2 + ahx) * 16);
                LDMATRIX_X4(al[0], al[1], al[2], al[3], clb + row * 272 + ((uint32_t)ks * 2 + ahx) * 16);
            }
#pragma unroll
            for (int nfp = 0; nfp < 2; nfp++) {
                int row = wp + nfp * 16 + brow;
                LDMATRIX_X4(bfr[nfp][0], bfr[nfp][1], bfr[nfp][2], bfr[nfp][3],
                            sinb + row * 272 + ((uint32_t)ks * 2 + bhx) * 16);
            }
#pragma unroll
            for (int nf = 0; nf < 4; nf++) {
                mma_f16(acco[nf], a, &bfr[nf >> 1][(nf & 1) * 2]);
                mma_f16(acco[nf], al, &bfr[nf >> 1][(nf & 1) * 2]);
            }
        }

        float dh = Dp[h];
        int t0 = wt + gID;
#pragma unroll
        for (int r = 0; r < 2; r++) {
            int t = t0 + r * 8;
            int tok = tok0 + t;
            float sc = expf(sa[t]);
            const float* projX = &g_proj[(size_t)tok * XPROJ + h * 64];
            const float* zrow = &g_xz[(size_t)tok * (2 * DINNER) + DINNER + h * 64];
            __half* yrow = &g_Yh[(size_t)tok * DINNER + h * 64];
#pragma unroll
            for (int nf = 0; nf < 4; nf++) {
                int p = wp + nf * 8 + tg * 2;
                float y0 = accd[nf][r * 2 + 0] + acco[nf][r * 2 + 0] * sc + projX[p] * dh;
                float y1 = accd[nf][r * 2 + 1] + acco[nf][r * 2 + 1] * sc + projX[p + 1] * dh;
                float z0 = zrow[p], z1 = zrow[p + 1];
                y0 *= z0 / (1.f + expf(-z0));
                y1 *= z1 / (1.f + expf(-z1));
                *(__half2*)&yrow[p] = __floats2half2_rn(y0, y1);
            }
        }
    }
}

// ============================================================================
// host side
// ============================================================================
typedef CUresult (*PFN_encode)(CUtensorMap*, CUtensorMapDataType, cuuint32_t, void*,
    const cuuint64_t*, const cuuint64_t*, const cuuint32_t*, const cuuint32_t*,
    CUtensorMapInterleave, CUtensorMapSwizzle, CUtensorMapL2promotion, CUtensorMapFloatOOBfill);

static PFN_encode get_encoder() {
    void* p = nullptr;
    cudaDriverEntryPointQueryResult qr;
#if CUDART_VERSION >= 12050
    cudaGetDriverEntryPointByVersion("cuTensorMapEncodeTiled", &p, 12000, cudaEnableDefault, &qr);
#else
    cudaGetDriverEntryPoint("cuTensorMapEncodeTiled", &p, cudaEnableDefault, &qr);
#endif
    return (PFN_encode)p;
}

static void make_map_h(PFN_encode enc, CUtensorMap* m, const void* ptr,
                       uint64_t d0, uint64_t d1, uint32_t b0, uint32_t b1)
{
    cuuint64_t dims[2] = { d0, d1 };
    cuuint64_t strides[1] = { d0 * 2 };
    cuuint32_t box[2] = { b0, b1 };
    cuuint32_t es[2] = { 1, 1 };
    enc(m, CU_TENSOR_MAP_DATA_TYPE_FLOAT16, 2, (void*)ptr, dims, strides, box, es,
        CU_TENSOR_MAP_INTERLEAVE_NONE, CU_TENSOR_MAP_SWIZZLE_128B,
        CU_TENSOR_MAP_L2_PROMOTION_L2_128B, CU_TENSOR_MAP_FLOAT_OOB_FILL_NONE);
}

extern "C" void kernel_launch(void* const* d_in, const int* in_sizes, int n_in,
                              void* d_out, int out_size)
{
    const float* x          = (const float*)d_in[0];
    const float* conv_w     = (const float*)d_in[2];
    const float* conv_b     = (const float*)d_in[3];
    const float* dt_proj_w  = (const float*)d_in[5];
    const float* dt_proj_b  = (const float*)d_in[6];
    const float* A_log      = (const float*)d_in[7];
    const float* Dp         = (const float*)d_in[8];
    float* out = (float*)d_out;

    void *p_xh, *p_wih, *p_wxh, *p_woh, *p_convh, *p_Yh;
    float *p_xz, *p_proj;
    cudaGetSymbolAddress(&p_xh,    g_xh);
    cudaGetSymbolAddress(&p_wih,   g_wih);
    cudaGetSymbolAddress(&p_wxh,   g_wxh);
    cudaGetSymbolAddress(&p_woh,   g_woh);
    cudaGetSymbolAddress(&p_convh, g_convh);
    cudaGetSymbolAddress(&p_Yh,    g_Yh);
    cudaGetSymbolAddress((void**)&p_xz,   g_xz);
    cudaGetSymbolAddress((void**)&p_proj, g_proj);

    cudaFuncSetAttribute(gemm_f16_mma,      cudaFuncAttributeMaxDynamicSharedMemorySize, GEMM_SMEM);
    cudaFuncSetAttribute(ssd_states_kernel, cudaFuncAttributeMaxDynamicSharedMemorySize, SST_SMEM);
    cudaFuncSetAttribute(ssd_out_kernel,    cudaFuncAttributeMaxDynamicSharedMemorySize, SO_SMEM);

    PFN_encode enc = get_encoder();
    CUtensorMap mA1, mB1, mA2, mB2, mA3, mB3;
    make_map_h(enc, &mA1, p_xh,    DMODEL, NTOK,       GBK, GBM);
    make_map_h(enc, &mB1, p_wih,   DMODEL, 2 * DINNER, GBK, GBN);
    make_map_h(enc, &mA2, p_convh, DINNER, NTOK,       GBK, GBM);
    make_map_h(enc, &mB2, p_wxh,   DINNER, XPROJ,      GBK, GBN);
    make_map_h(enc, &mA3, p_Yh,    DINNER, NTOK,       GBK, GBM);
    make_map_h(enc, &mB3, p_woh,   DINNER, DMODEL,     GBK, GBN);

    to_half_kernel<<<(NTOK * DMODEL / 4 + 255) / 256, 256>>>((const float4*)x, (uint2*)p_xh, NTOK * DMODEL / 4);
    to_half_kernel<<<(2 * DINNER * DMODEL / 4 + 255) / 256, 256>>>((const float4*)d_in[1], (uint2*)p_wih, 2 * DINNER * DMODEL / 4);
    to_half_kernel<<<((int)((size_t)XPROJ * DINNER / 4) + 255) / 256, 256>>>((const float4*)d_in[4], (uint2*)p_wxh, (int)((size_t)XPROJ * DINNER / 4));
    to_half_kernel<<<(DMODEL * DINNER / 4 + 255) / 256, 256>>>((const float4*)d_in[9], (uint2*)p_woh, DMODEL * DINNER / 4);

    // 1) xz = x @ in_proj_w^T  (fp32 out — dt path amplifies rounding via exp(cumsum))
    gemm_f16_mma<<<dim3(2 * DINNER / GBN, NTOK / GBM), 256, GEMM_SMEM>>>(mA1, mB1, p_xz, 2 * DINNER, DMODEL);
    // 2) depthwise conv + bias + silu (fp16 out, 2 ch/thread)
    conv_silu_kernel<<<(NTOK * DINNER / 2) / 256, 256>>>(conv_w, conv_b);
    // 3) proj = conv @ x_proj_w^T (fp32 out)
    gemm_f16_mma<<<dim3((XPROJ + GBN - 1) / GBN, NTOK / GBM), 256, GEMM_SMEM>>>(mA2, mB2, p_proj, XPROJ, DINNER);
    // 4) dt
    dt_kernel<<<NTOK / 4, 256>>>(dt_proj_w, dt_proj_b, A_log);
    // 5) per-chunk local states (split MMA, fp16 states out)
    ssd_states_kernel<<<BATCH * NCHUNK * NHEADS, 256, SST_SMEM>>>();
    // 6) inter-chunk scan (fp16 states, fp32 carry)
    ssd_scan_kernel<<<BATCH * NHEADS * 8, 256>>>();
    // 7) SSD output + gating (split MMA, fp16 out)
    ssd_out_kernel<<<BATCH * NCHUNK * NHEADS, 256, SO_SMEM>>>(Dp);
    // 8) out = Y @ out_proj_w^T (fp32 out)
    gemm_f16_mma<<<dim3(DMODEL / GBN, NTOK / GBM), 256, GEMM_SMEM>>>(mA3, mB3, out, DMODEL, DINNER);
}

// round 17
// speedup vs baseline: 1.0020x; 1.0009x over previous
#include <cuda_runtime.h>
#include <cuda.h>
#include <cuda_fp16.h>
#include <math.h>
#include <stdint.h>

// ---------------- problem constants ----------------
#define BATCH   2
#define SEQLEN  4096
#define DMODEL  2048
#define DINNER  4096
#define NHEADS  64
#define HEADDIM 64
#define DSTATE  128
#define CHUNKL  64
#define NCHUNK  64
#define XPROJ   4416
#define NTOK    (BATCH*SEQLEN)   // 8192

// ---------------- scratch (device globals; no allocs allowed) ----------------
__device__ float g_xz[(size_t)NTOK * 2 * DINNER];     // fp32 (x_branch | z_branch)
__device__ float g_proj[(size_t)NTOK * XPROJ];
__device__ float g_dt[NTOK * NHEADS];
__device__ float g_dA[NTOK * NHEADS];
__device__ __half g_statesh[(size_t)BATCH * NCHUNK * NHEADS * HEADDIM * DSTATE];
// fp16 GEMM inputs
__device__ __half g_xh[(size_t)NTOK * DMODEL];
__device__ __half g_wih[(size_t)2 * DINNER * DMODEL];
__device__ __half g_wxh[(size_t)XPROJ * DINNER];
__device__ __half g_woh[(size_t)DMODEL * DINNER];
__device__ __half g_convh[(size_t)NTOK * DINNER];
__device__ __half g_Yh[(size_t)NTOK * DINNER];

// ============================================================================
// PTX helpers (baseline sm_80/sm_90 features only)
// ============================================================================
__device__ __forceinline__ uint32_t smem_u32(const void* p) {
    uint32_t a;
    asm("{ .reg .u64 t; cvta.to.shared.u64 t, %1; cvt.u32.u64 %0, t; }" : "=r"(a) : "l"(p));
    return a;
}

#define MBARRIER_INIT(addr, cnt) \
    asm volatile("mbarrier.init.shared.b64 [%0], %1;" :: "r"((uint32_t)(addr)), "r"((uint32_t)(cnt)) : "memory")

#define MBARRIER_EXPECT_TX(addr, bytes) \
    asm volatile("mbarrier.arrive.expect_tx.shared.b64 _, [%0], %1;" :: "r"((uint32_t)(addr)), "r"((uint32_t)(bytes)) : "memory")

#define MBARRIER_ARRIVE(addr) \
    asm volatile("mbarrier.arrive.shared.b64 _, [%0];" :: "r"((uint32_t)(addr)) : "memory")

#define MBARRIER_WAIT_PARITY(addr, parity) do {                                    \
    uint32_t _m = (uint32_t)(addr); uint32_t _p = (uint32_t)(parity); uint32_t _d; \
    asm volatile("{\n\t.reg .pred p;\n\t"                                          \
        "mbarrier.try_wait.parity.acquire.cta.shared::cta.b64 p, [%1], %2;\n\t"    \
        "selp.b32 %0, 1, 0, p;\n\t}"                                               \
        : "=r"(_d) : "r"(_m), "r"(_p) : "memory");                                 \
    if (!_d) {                                                                     \
        asm volatile("{\n\t.reg .pred P1;\n\t"                                     \
            "WL_%=:\n\t"                                                           \
            "mbarrier.try_wait.parity.acquire.cta.shared::cta.b64 P1, [%0], %1, 0x989680;\n\t" \
            "@P1 bra.uni WD_%=;\n\t"                                               \
            "bra.uni WL_%=;\n\t"                                                   \
            "WD_%=:\n\t}"                                                          \
            :: "r"(_m), "r"(_p) : "memory");                                       \
    }                                                                              \
} while (0)

#define FENCE_PROXY_ASYNC()   asm volatile("fence.proxy.async;" ::: "memory")

__device__ __forceinline__ void tma2d(uint32_t smem, const CUtensorMap* map,
                                      int cx, int cy, uint32_t mbar) {
    asm volatile(
        "cp.async.bulk.tensor.2d.shared::cta.global.tile.mbarrier::complete_tx::bytes "
        "[%0], [%1, {%2, %3}], [%4];"
        :: "r"(smem), "l"(map), "r"(cx), "r"(cy), "r"(mbar) : "memory");
}

#define LDMATRIX_X4(r0, r1, r2, r3, addr) \
    asm volatile("ldmatrix.sync.aligned.m8n8.x4.shared.b16 {%0,%1,%2,%3}, [%4];" \
        : "=r"(r0), "=r"(r1), "=r"(r2), "=r"(r3) : "r"(addr))

// mma m16n8k16 fp16 in, fp32 accum (sm_80+ baseline)
__device__ __forceinline__ void mma_f16(float* d, const uint32_t* a, const uint32_t* b) {
    asm volatile(
        "mma.sync.aligned.m16n8k16.row.col.f32.f16.f16.f32 "
        "{%0,%1,%2,%3}, {%4,%5,%6,%7}, {%8,%9}, {%0,%1,%2,%3};"
        : "+f"(d[0]), "+f"(d[1]), "+f"(d[2]), "+f"(d[3])
        : "r"(a[0]), "r"(a[1]), "r"(a[2]), "r"(a[3]), "r"(b[0]), "r"(b[1]));
}

__device__ __forceinline__ void split_h(float v, __half& hi, __half& lo) {
    hi = __float2half_rn(v);
    lo = __float2half_rn(v - __half2float(hi));
}

// ============================================================================
// fp16 HMMA GEMM: C[m,n] = sum_k A[m,k]*W[n,k]  (A,W fp16; C fp32)
// CTA tile 128x128, BK=64, 3-stage TMA pipeline (R7-proven refill structure:
// refill strictly AFTER the stage's own drain is confirmed — race-free).
// ============================================================================
#define GSTAGES 3
#define GBM 128
#define GBN 128
#define GBK 64
#define STAGE_BYTES  32768
#define SM_A(s)  ((s) * STAGE_BYTES)
#define SM_B(s)  ((s) * STAGE_BYTES + 16384)
#define MB_BASE  (GSTAGES * STAGE_BYTES)
#define MB_FULL(s)  (MB_BASE + 8 * (s))
#define MB_EMPTY(s) (MB_BASE + 32 + 8 * (s))
#define GEMM_SMEM   (MB_BASE + 128)

__global__ __launch_bounds__(256, 2) void gemm_f16_mma(
    const __grid_constant__ CUtensorMap tma_a,
    const __grid_constant__ CUtensorMap tma_b,
    float* __restrict__ C, int N, int K)
{
    extern __shared__ __align__(1024) char smem_raw[];
    uint32_t sb = smem_u32(smem_raw);
    const int tid = threadIdx.x;
    const int lane = tid & 31, wid = tid >> 5;
    const int wm = (wid & 1) * 64;
    const int wn = (wid >> 1) * 32;
    const int m0 = blockIdx.y * GBM;
    const int n0 = blockIdx.x * GBN;

    const int arow = lane & 15;
    const uint32_t ahi = lane >> 4;
    const int brow = (lane & 7) + ((lane >> 4) << 3);
    const uint32_t bhi = (lane >> 3) & 1;

    if (tid == 0) {
        for (int s = 0; s < GSTAGES; s++) {
            MBARRIER_INIT(sb + MB_FULL(s), 1);
            MBARRIER_INIT(sb + MB_EMPTY(s), 8);
        }
        FENCE_PROXY_ASYNC();
    }
    __syncthreads();

    const int KT = K / GBK;

    if (tid == 0) {
        for (int s = 0; s < GSTAGES; s++) {
            MBARRIER_EXPECT_TX(sb + MB_FULL(s), STAGE_BYTES);
            tma2d(sb + SM_A(s), &tma_a, s * GBK, m0, sb + MB_FULL(s));
            tma2d(sb + SM_B(s), &tma_b, s * GBK, n0, sb + MB_FULL(s));
        }
    }

    float acc[4][4][4];
#pragma unroll
    for (int i = 0; i < 4; i++)
#pragma unroll
        for (int j = 0; j < 4; j++)
#pragma unroll
            for (int v = 0; v < 4; v++) acc[i][j][v] = 0.f;

    int st = 0, ph = 0;
    for (int kt = 0; kt < KT; kt++) {
        MBARRIER_WAIT_PARITY(sb + MB_FULL(st), ph);
        const uint32_t sA = sb + SM_A(st);
        const uint32_t sB = sb + SM_B(st);

#pragma unroll
        for (int ks = 0; ks < 4; ks++) {
            uint32_t a[4][4], b[2][4];
#pragma unroll
            for (int mf = 0; mf < 4; mf++) {
                int row = wm + mf * 16 + arow;
                uint32_t addr = sA + row * 128 + ((((uint32_t)ks * 2 + ahi) ^ (row & 7)) << 4);
                LDMATRIX_X4(a[mf][0], a[mf][1], a[mf][2], a[mf][3], addr);
            }
#pragma unroll
            for (int nfp = 0; nfp < 2; nfp++) {
                int row = wn + nfp * 16 + brow;
                uint32_t addr = sB + row * 128 + ((((uint32_t)ks * 2 + bhi) ^ (row & 7)) << 4);
                LDMATRIX_X4(b[nfp][0], b[nfp][1], b[nfp][2], b[nfp][3], addr);
            }
#pragma unroll
            for (int mf = 0; mf < 4; mf++)
#pragma unroll
                for (int nf = 0; nf < 4; nf++)
                    mma_f16(acc[mf][nf], a[mf], &b[nf >> 1][(nf & 1) * 2]);
        }

        if (lane == 0) MBARRIER_ARRIVE(sb + MB_EMPTY(st));
        if (tid == 0 && kt + GSTAGES < KT) {
            MBARRIER_WAIT_PARITY(sb + MB_EMPTY(st), ph);
            MBARRIER_EXPECT_TX(sb + MB_FULL(st), STAGE_BYTES);
            tma2d(sb + SM_A(st), &tma_a, (kt + GSTAGES) * GBK, m0, sb + MB_FULL(st));
            tma2d(sb + SM_B(st), &tma_b, (kt + GSTAGES) * GBK, n0, sb + MB_FULL(st));
        }
        if (++st == GSTAGES) { st = 0; ph ^= 1; }
    }

    const int gID = lane >> 2, tg = lane & 3;
#pragma unroll
    for (int mf = 0; mf < 4; mf++) {
        const int row = m0 + wm + mf * 16 + gID;
#pragma unroll
        for (int nf = 0; nf < 4; nf++) {
            const int col = n0 + wn + nf * 8 + tg * 2;
            if (col < N) {
                *(float2*)&C[(size_t)row * N + col] = make_float2(acc[mf][nf][0], acc[mf][nf][1]);
                *(float2*)&C[(size_t)(row + 8) * N + col] = make_float2(acc[mf][nf][2], acc[mf][nf][3]);
            }
        }
    }
}

// ---------------- fp32 -> fp16 RN conversion ----------------
__global__ void to_half_kernel(const float4* __restrict__ in, uint2* __restrict__ out, int n4)
{
    int i = blockIdx.x * blockDim.x + threadIdx.x;
    if (i < n4) {
        float4 v = in[i];
        __half2 h0 = __floats2half2_rn(v.x, v.y);
        __half2 h1 = __floats2half2_rn(v.z, v.w);
        uint2 r;
        r.x = *reinterpret_cast<uint32_t*>(&h0);
        r.y = *reinterpret_cast<uint32_t*>(&h1);
        out[i] = r;
    }
}

// ---------------- depthwise causal conv (D_CONV=4) + bias + SiLU -> fp16 -----
// 2 channels per thread (vectorized; per-channel math identical to scalar).
__global__ void conv_silu_kernel(const float* __restrict__ convw,
                                 const float* __restrict__ convb)
{
    int idx2 = blockIdx.x * blockDim.x + threadIdx.x;        // pair index
    if (idx2 >= NTOK * DINNER / 2) return;
    int c = (idx2 << 1) & (DINNER - 1);                      // even channel
    int tok = idx2 >> 11;                                    // /(DINNER/2)
    int t = tok & (SEQLEN - 1);
    float2 bias = *(const float2*)&convb[c];
    float y0 = bias.x, y1 = bias.y;
    float2 w0 = *(const float2*)&convw[c * 4];               // convw[c][0..1]
    float2 w1 = *(const float2*)&convw[c * 4 + 2];           // convw[c][2..3]
    float2 w2 = *(const float2*)&convw[(c + 1) * 4];         // convw[c+1][0..1]
    float2 w3 = *(const float2*)&convw[(c + 1) * 4 + 2];     // convw[c+1][2..3]
    float wA[4] = { w0.x, w0.y, w1.x, w1.y };
    float wB[4] = { w2.x, w2.y, w3.x, w3.y };
#pragma unroll
    for (int j = 0; j < 4; j++) {
        int tt = t - 3 + j;
        if (tt >= 0) {
            float2 xv = *(const float2*)&g_xz[(size_t)(tok - 3 + j) * (2 * DINNER) + c];
            y0 = fmaf(wA[j], xv.x, y0);
            y1 = fmaf(wB[j], xv.y, y1);
        }
    }
    float s0 = y0 / (1.f + expf(-y0));
    float s1 = y1 / (1.f + expf(-y1));
    *(__half2*)&g_convh[(size_t)tok * DINNER + c] = __floats2half2_rn(s0, s1);
}

// ---------------- dt projection + softplus; dA = -exp(A_log)*dt --------------
__global__ __launch_bounds__(256) void dt_kernel(const float* __restrict__ dtw,
                                                 const float* __restrict__ dtb,
                                                 const float* __restrict__ A_log)
{
    int sub = threadIdx.x >> 6;
    int h = threadIdx.x & 63;
    int tok = blockIdx.x * 4 + sub;
    __shared__ float raw[4][64];
    raw[sub][h] = g_proj[(size_t)tok * XPROJ + DINNER + h];
    __syncthreads();
    float acc = dtb[h];
#pragma unroll
    for (int k = 0; k < 64; k++) acc = fmaf(dtw[h * 64 + k], raw[sub][k], acc);
    float dt = (acc > 20.f) ? acc : log1pf(expf(acc));
    g_dt[tok * 64 + h] = dt;
    g_dA[tok * 64 + h] = -expf(A_log[h]) * dt;
}

// ============================================================================
// per-chunk local states via split-operand MMA:
// S[p][n] = sum_t Xd[t][p] * B[t][n];  Xd split hi/lo (22-bit effective)
// ============================================================================
#define SST_SBT   0                        // halves
#define SST_SXT   (128 * 72)               // 9216
#define SST_SXTL  (SST_SXT + 64 * 72)      // 13824
#define SST_SA    (SST_SXTL + 64 * 72)     // 18432 halves
#define SST_SMEM  ((SST_SA + 128) * 2)     // bytes

__global__ __launch_bounds__(256) void ssd_states_kernel()
{
    extern __shared__ __align__(16) __half smh[];
    __half* sBT   = smh + SST_SBT;
    __half* sXdT  = smh + SST_SXT;
    __half* sXdTL = smh + SST_SXTL;
    float* sa = (float*)(smh + SST_SA);
    int bid = blockIdx.x;
    int h = bid & 63, c = (bid >> 6) & 63, b = bid >> 12;
    int tok0 = b * SEQLEN + c * CHUNKL;
    int tid = threadIdx.x;
    const int lane = tid & 31, wid = tid >> 5;

    if (tid < 64) sa[tid] = g_dA[(tok0 + tid) * NHEADS + h];
    __syncthreads();
    if (tid == 0) { float s = 0.f; for (int t = 0; t < 64; t++) { s += sa[t]; sa[t] = s; } }
    __syncthreads();
    float alast = sa[63];

    for (int i = tid; i < 8192; i += 256) {
        int t = i >> 7, n = i & 127;
        sBT[n * 72 + t] = __float2half_rn(g_proj[(size_t)(tok0 + t) * XPROJ + (DINNER + NHEADS) + n]);
    }
    for (int i = tid; i < 4096; i += 256) {
        int t = i >> 6, p = i & 63;
        float v = g_proj[(size_t)(tok0 + t) * XPROJ + h * 64 + p]
                * g_dt[(tok0 + t) * NHEADS + h] * expf(alast - sa[t]);
        __half hi, lo; split_h(v, hi, lo);
        sXdT[p * 72 + t] = hi;
        sXdTL[p * 72 + t] = lo;
    }
    __syncthreads();

    const int arow = lane & 15;
    const uint32_t ahx = lane >> 4;
    const int brow = (lane & 7) + ((lane >> 4) << 3);
    const uint32_t bhx = (lane >> 3) & 1;
    const int wm = (wid & 1) * 32;     // p
    const int wn = (wid >> 1) * 32;    // n

    uint32_t xb = smem_u32(sXdT), xlb = smem_u32(sXdTL), bb = smem_u32(sBT);
    float acc[2][4][4];
#pragma unroll
    for (int i = 0; i < 2; i++)
#pragma unroll
        for (int j = 0; j < 4; j++)
#pragma unroll
            for (int v = 0; v < 4; v++) acc[i][j][v] = 0.f;

#pragma unroll
    for (int ks = 0; ks < 4; ks++) {
        uint32_t a[2][4], al[2][4], bfr[2][4];
#pragma unroll
        for (int mf = 0; mf < 2; mf++) {
            int row = wm + mf * 16 + arow;
            LDMATRIX_X4(a[mf][0], a[mf][1], a[mf][2], a[mf][3],
                        xb + row * 144 + ((uint32_t)ks * 2 + ahx) * 16);
            LDMATRIX_X4(al[mf][0], al[mf][1], al[mf][2], al[mf][3],
                        xlb + row * 144 + ((uint32_t)ks * 2 + ahx) * 16);
        }
#pragma unroll
        for (int nfp = 0; nfp < 2; nfp++) {
            int row = wn + nfp * 16 + brow;
            LDMATRIX_X4(bfr[nfp][0], bfr[nfp][1], bfr[nfp][2], bfr[nfp][3],
                        bb + row * 144 + ((uint32_t)ks * 2 + bhx) * 16);
        }
#pragma unroll
        for (int mf = 0; mf < 2; mf++)
#pragma unroll
            for (int nf = 0; nf < 4; nf++) {
                mma_f16(acc[mf][nf], a[mf], &bfr[nf >> 1][(nf & 1) * 2]);
                mma_f16(acc[mf][nf], al[mf], &bfr[nf >> 1][(nf & 1) * 2]);
            }
    }

    const int gID = lane >> 2, tg = lane & 3;
    size_t outbase = ((size_t)((b * 64 + c) * 64 + h)) * 8192;
#pragma unroll
    for (int mf = 0; mf < 2; mf++) {
        int p = wm + mf * 16 + gID;
#pragma unroll
        for (int nf = 0; nf < 4; nf++) {
            int n = wn + nf * 8 + tg * 2;
            *(__half2*)&g_statesh[outbase + (size_t)p * 128 + n] =
                __floats2half2_rn(acc[mf][nf][0], acc[mf][nf][1]);
            *(__half2*)&g_statesh[outbase + (size_t)(p + 8) * 128 + n] =
                __floats2half2_rn(acc[mf][nf][2], acc[mf][nf][3]);
        }
    }
}

// ---------------- inter-chunk sequential scan (fp16 states, fp32 carry) ------
__global__ __launch_bounds__(256) void ssd_scan_kernel()
{
    __shared__ float alast[64];
    int blk = blockIdx.x;
    int slice = blk & 7;
    int bh = blk >> 3;
    int b = bh >> 6, h = bh & 63;
    int tid = threadIdx.x;
    if (tid < 64) {
        int c = tid;
        int tok0 = b * SEQLEN + c * CHUNKL;
        float s = 0.f;
        for (int t = 0; t < 64; t++) s += g_dA[(tok0 + t) * NHEADS + h];
        alast[c] = expf(s);
    }
    __syncthreads();
    float run0 = 0.f, run1 = 0.f, run2 = 0.f, run3 = 0.f;
    int off = slice * 1024 + tid * 4;
    for (int c = 0; c < 64; c++) {
        size_t base = ((size_t)((b * 64 + c) * 64 + h)) * 8192 + off;
        float dec = alast[c];
        uint2 v = *(const uint2*)&g_statesh[base];
        __half2 l0 = *reinterpret_cast<__half2*>(&v.x);
        __half2 l1 = *reinterpret_cast<__half2*>(&v.y);
        float2 f0 = __half22float2(l0);
        float2 f1 = __half22float2(l1);
        __half2 e0 = __floats2half2_rn(run0, run1);
        __half2 e1 = __floats2half2_rn(run2, run3);
        uint2 w;
        w.x = *reinterpret_cast<uint32_t*>(&e0);
        w.y = *reinterpret_cast<uint32_t*>(&e1);
        *(uint2*)&g_statesh[base] = w;
        run0 = fmaf(dec, run0, f0.x);
        run1 = fmaf(dec, run1, f0.y);
        run2 = fmaf(dec, run2, f1.x);
        run3 = fmaf(dec, run3, f1.y);
    }
}

// ============================================================================
// SSD output via split-operand MMA:
//  G = mask * (C @ B^T) * decay   (C split hi/lo; G stored hi/lo)
//  Y = G @ X  +  exp(sa[t]) * (C @ Sin^T)  + X*D, gated by silu(z)
// ============================================================================
#define SO_C    0
#define SO_CLO  (64 * 136)               // 8704
#define SO_B    (2 * 64 * 136)           // 17408
#define SO_SIN  (3 * 64 * 136)           // 26112
#define SO_XT   (4 * 64 * 136)           // 34816
#define SO_G    (SO_XT + 64 * 72)        // 39424
#define SO_GLO  (SO_G + 64 * 72)         // 44032
#define SO_SA   (SO_GLO + 64 * 72)       // 48640 halves
#define SO_SMEM ((SO_SA + 128) * 2)      // 97536 bytes

__global__ __launch_bounds__(256) void ssd_out_kernel(const float* __restrict__ Dp)
{
    extern __shared__ __align__(16) __half smh[];
    __half* sC   = smh + SO_C;
    __half* sCL  = smh + SO_CLO;
    __half* sB   = smh + SO_B;
    __half* sSin = smh + SO_SIN;
    __half* sXT  = smh + SO_XT;
    __half* sG   = smh + SO_G;
    __half* sGL  = smh + SO_GLO;
    float*  sa   = (float*)(smh + SO_SA);

    int bid = blockIdx.x;
    int h = bid & 63, c = (bid >> 6) & 63, b = bid >> 12;
    int tok0 = b * SEQLEN + c * CHUNKL;
    int tid = threadIdx.x;
    const int lane = tid & 31, wid = tid >> 5;

    if (tid < 64) sa[tid] = g_dA[(tok0 + tid) * NHEADS + h];
    __syncthreads();
    if (tid == 0) { float s = 0.f; for (int t = 0; t < 64; t++) { s += sa[t]; sa[t] = s; } }

    size_t sbase = ((size_t)((b * 64 + c) * 64 + h)) * 8192;
    for (int i = tid; i < 8192; i += 256) {
        int t = i >> 7, n = i & 127;
        float cv = g_proj[(size_t)(tok0 + t) * XPROJ + (DINNER + NHEADS + DSTATE) + n];
        __half chi, clo; split_h(cv, chi, clo);
        sC[t * 136 + n]  = chi;
        sCL[t * 136 + n] = clo;
        sB[t * 136 + n]  = __float2half_rn(g_proj[(size_t)(tok0 + t) * XPROJ + (DINNER + NHEADS) + n]);
        sSin[t * 136 + n] = g_statesh[sbase + i];    // t here is p
    }
    for (int i = tid; i < 4096; i += 256) {
        int t = i >> 6, p = i & 63;
        float v = g_proj[(size_t)(tok0 + t) * XPROJ + h * 64 + p] * g_dt[(tok0 + t) * NHEADS + h];
        sXT[p * 72 + t] = __float2half_rn(v);
    }
    __syncthreads();

    const int arow = lane & 15;
    const uint32_t ahx = lane >> 4;
    const int brow = (lane & 7) + ((lane >> 4) << 3);
    const uint32_t bhx = (lane >> 3) & 1;
    const int gID = lane >> 2, tg = lane & 3;

    uint32_t cb = smem_u32(sC), clb = smem_u32(sCL), bb = smem_u32(sB), sinb = smem_u32(sSin);
    uint32_t xtb = smem_u32(sXT), gb = smem_u32(sG), glb = smem_u32(sGL);

    // ---- phase 1: G = (Chi+Clo) @ B^T, masked + decay, store hi/lo fp16 ----
    {
        const int wt = (wid & 3) * 16;     // t
        const int ws = (wid >> 2) * 32;    // s
        float gacc[4][4];
#pragma unroll
        for (int j = 0; j < 4; j++)
#pragma unroll
            for (int v = 0; v < 4; v++) gacc[j][v] = 0.f;

#pragma unroll
        for (int ks = 0; ks < 8; ks++) {
            uint32_t a[4], al[4], bfr[2][4];
            {
                int row = wt + arow;
                LDMATRIX_X4(a[0], a[1], a[2], a[3], cb + row * 272 + ((uint32_t)ks * 2 + ahx) * 16);
                LDMATRIX_X4(al[0], al[1], al[2], al[3], clb + row * 272 + ((uint32_t)ks * 2 + ahx) * 16);
            }
#pragma unroll
            for (int nfp = 0; nfp < 2; nfp++) {
                int row = ws + nfp * 16 + brow;
                LDMATRIX_X4(bfr[nfp][0], bfr[nfp][1], bfr[nfp][2], bfr[nfp][3],
                            bb + row * 272 + ((uint32_t)ks * 2 + bhx) * 16);
            }
#pragma unroll
            for (int nf = 0; nf < 4; nf++) {
                mma_f16(gacc[nf], a, &bfr[nf >> 1][(nf & 1) * 2]);
                mma_f16(gacc[nf], al, &bfr[nf >> 1][(nf & 1) * 2]);
            }
        }

        int t0 = wt + gID, t1 = t0 + 8;
        float e0 = sa[t0], e1 = sa[t1];
#pragma unroll
        for (int nf = 0; nf < 4; nf++) {
            int s0 = ws + nf * 8 + tg * 2;
            float es0 = sa[s0], es1 = sa[s0 + 1];
            float v00 = (s0     <= t0) ? gacc[nf][0] * expf(e0 - es0) : 0.f;
            float v01 = (s0 + 1 <= t0) ? gacc[nf][1] * expf(e0 - es1) : 0.f;
            float v10 = (s0     <= t1) ? gacc[nf][2] * expf(e1 - es0) : 0.f;
            float v11 = (s0 + 1 <= t1) ? gacc[nf][3] * expf(e1 - es1) : 0.f;
            __half h00, l00, h01, l01, h10, l10, h11, l11;
            split_h(v00, h00, l00); split_h(v01, h01, l01);
            split_h(v10, h10, l10); split_h(v11, h11, l11);
            *(__half2*)&sG[t0 * 72 + s0]  = __halves2half2(h00, h01);
            *(__half2*)&sGL[t0 * 72 + s0] = __halves2half2(l00, l01);
            *(__half2*)&sG[t1 * 72 + s0]  = __halves2half2(h10, h11);
            *(__half2*)&sGL[t1 * 72 + s0] = __halves2half2(l10, l11);
        }
    }
    __syncthreads();

    // ---- phase 2: Y = (Ghi+Glo)@X + exp(sa[t]) * ((Chi+Clo)@Sin^T) ----
    {
        const int wt = (wid & 3) * 16;     // t
        const int wp = (wid >> 2) * 32;    // p
        float accd[4][4], acco[4][4];
#pragma unroll
        for (int j = 0; j < 4; j++)
#pragma unroll
            for (int v = 0; v < 4; v++) { accd[j][v] = 0.f; acco[j][v] = 0.f; }

        // diag: A = G[t][s] (k=s,64) split, B = sXT[p][s]
#pragma unroll
        for (int ks = 0; ks < 4; ks++) {
            uint32_t a[4], al[4], bfr[2][4];
            {
                int row = wt + arow;
                LDMATRIX_X4(a[0], a[1], a[2], a[3], gb + row * 144 + ((uint32_t)ks * 2 + ahx) * 16);
                LDMATRIX_X4(al[0], al[1], al[2], al[3], glb + row * 144 + ((uint32_t)ks * 2 + ahx) * 16);
            }
#pragma unroll
            for (int nfp = 0; nfp < 2; nfp++) {
                int row = wp + nfp * 16 + brow;
                LDMATRIX_X4(bfr[nfp][0], bfr[nfp][1], bfr[nfp][2], bfr[nfp][3],
                            xtb + row * 144 + ((uint32_t)ks * 2 + bhx) * 16);
            }
#pragma unroll
            for (int nf = 0; nf < 4; nf++) {
                mma_f16(accd[nf], a, &bfr[nf >> 1][(nf & 1) * 2]);
                mma_f16(accd[nf], al, &bfr[nf >> 1][(nf & 1) * 2]);
            }
        }

        // off: A = C[t][n] (k=n,128) split, B = sSin[p][n]
#pragma unroll
        for (int ks = 0; ks < 8; ks++) {
            uint32_t a[4], al[4], bfr[2][4];
            {
                int row = wt + arow;
                LDMATRIX_X4(a[0], a[1], a[2], a[3], cb + row * 272 + ((uint32_t)ks * 2 + ahx) * 16);
                LDMATRIX_X4(al[0], al[1], al[2], al[3], clb + row * 272 + ((uint32_t)ks * 2 + ahx) * 16);
            }
#pragma unroll
            for (int nfp = 0; nfp < 2; nfp++) {
                int row = wp + nfp * 16 + brow;
                LDMATRIX_X4(bfr[nfp][0], bfr[nfp][1], bfr[nfp][2], bfr[nfp][3],
                            sinb + row * 272 + ((uint32_t)ks * 2 + bhx) * 16);
            }
#pragma unroll
            for (int nf = 0; nf < 4; nf++) {
                mma_f16(acco[nf], a, &bfr[nf >> 1][(nf & 1) * 2]);
                mma_f16(acco[nf], al, &bfr[nf >> 1][(nf & 1) * 2]);
            }
        }

        float dh = Dp[h];
        int t0 = wt + gID;
#pragma unroll
        for (int r = 0; r < 2; r++) {
            int t = t0 + r * 8;
            int tok = tok0 + t;
            float sc = expf(sa[t]);
            const float* projX = &g_proj[(size_t)tok * XPROJ + h * 64];
            const float* zrow = &g_xz[(size_t)tok * (2 * DINNER) + DINNER + h * 64];
            __half* yrow = &g_Yh[(size_t)tok * DINNER + h * 64];
#pragma unroll
            for (int nf = 0; nf < 4; nf++) {
                int p = wp + nf * 8 + tg * 2;
                float y0 = accd[nf][r * 2 + 0] + acco[nf][r * 2 + 0] * sc + projX[p] * dh;
                float y1 = accd[nf][r * 2 + 1] + acco[nf][r * 2 + 1] * sc + projX[p + 1] * dh;
                float z0 = zrow[p], z1 = zrow[p + 1];
                y0 *= z0 / (1.f + expf(-z0));
                y1 *= z1 / (1.f + expf(-z1));
                *(__half2*)&yrow[p] = __floats2half2_rn(y0, y1);
            }
        }
    }
}

// ============================================================================
// host side
// ============================================================================
typedef CUresult (*PFN_encode)(CUtensorMap*, CUtensorMapDataType, cuuint32_t, void*,
    const cuuint64_t*, const cuuint64_t*, const cuuint32_t*, const cuuint32_t*,
    CUtensorMapInterleave, CUtensorMapSwizzle, CUtensorMapL2promotion, CUtensorMapFloatOOBfill);

static PFN_encode get_encoder() {
    void* p = nullptr;
    cudaDriverEntryPointQueryResult qr;
#if CUDART_VERSION >= 12050
    cudaGetDriverEntryPointByVersion("cuTensorMapEncodeTiled", &p, 12000, cudaEnableDefault, &qr);
#else
    cudaGetDriverEntryPoint("cuTensorMapEncodeTiled", &p, cudaEnableDefault, &qr);
#endif
    return (PFN_encode)p;
}

static void make_map_h(PFN_encode enc, CUtensorMap* m, const void* ptr,
                       uint64_t d0, uint64_t d1, uint32_t b0, uint32_t b1)
{
    cuuint64_t dims[2] = { d0, d1 };
    cuuint64_t strides[1] = { d0 * 2 };
    cuuint32_t box[2] = { b0, b1 };
    cuuint32_t es[2] = { 1, 1 };
    enc(m, CU_TENSOR_MAP_DATA_TYPE_FLOAT16, 2, (void*)ptr, dims, strides, box, es,
        CU_TENSOR_MAP_INTERLEAVE_NONE, CU_TENSOR_MAP_SWIZZLE_128B,
        CU_TENSOR_MAP_L2_PROMOTION_L2_128B, CU_TENSOR_MAP_FLOAT_OOB_FILL_NONE);
}

extern "C" void kernel_launch(void* const* d_in, const int* in_sizes, int n_in,
                              void* d_out, int out_size)
{
    const float* x          = (const float*)d_in[0];
    const float* conv_w     = (const float*)d_in[2];
    const float* conv_b     = (const float*)d_in[3];
    const float* dt_proj_w  = (const float*)d_in[5];
    const float* dt_proj_b  = (const float*)d_in[6];
    const float* A_log      = (const float*)d_in[7];
    const float* Dp         = (const float*)d_in[8];
    float* out = (float*)d_out;

    void *p_xh, *p_wih, *p_wxh, *p_woh, *p_convh, *p_Yh;
    float *p_xz, *p_proj;
    cudaGetSymbolAddress(&p_xh,    g_xh);
    cudaGetSymbolAddress(&p_wih,   g_wih);
    cudaGetSymbolAddress(&p_wxh,   g_wxh);
    cudaGetSymbolAddress(&p_woh,   g_woh);
    cudaGetSymbolAddress(&p_convh, g_convh);
    cudaGetSymbolAddress(&p_Yh,    g_Yh);
    cudaGetSymbolAddress((void**)&p_xz,   g_xz);
    cudaGetSymbolAddress((void**)&p_proj, g_proj);

    cudaFuncSetAttribute(gemm_f16_mma,      cudaFuncAttributeMaxDynamicSharedMemorySize, GEMM_SMEM);
    cudaFuncSetAttribute(ssd_states_kernel, cudaFuncAttributeMaxDynamicSharedMemorySize, SST_SMEM);
    cudaFuncSetAttribute(ssd_out_kernel,    cudaFuncAttributeMaxDynamicSharedMemorySize, SO_SMEM);

    PFN_encode enc = get_encoder();
    CUtensorMap mA1, mB1, mA2, mB2, mA3, mB3;
    make_map_h(enc, &mA1, p_xh,    DMODEL, NTOK,       GBK, GBM);
    make_map_h(enc, &mB1, p_wih,   DMODEL, 2 * DINNER, GBK, GBN);
    make_map_h(enc, &mA2, p_convh, DINNER, NTOK,       GBK, GBM);
    make_map_h(enc, &mB2, p_wxh,   DINNER, XPROJ,      GBK, GBN);
    make_map_h(enc, &mA3, p_Yh,    DINNER, NTOK,       GBK, GBM);
    make_map_h(enc, &mB3, p_woh,   DINNER, DMODEL,     GBK, GBN);

    to_half_kernel<<<(NTOK * DMODEL / 4 + 255) / 256, 256>>>((const float4*)x, (uint2*)p_xh, NTOK * DMODEL / 4);
    to_half_kernel<<<(2 * DINNER * DMODEL / 4 + 255) / 256, 256>>>((const float4*)d_in[1], (uint2*)p_wih, 2 * DINNER * DMODEL / 4);
    to_half_kernel<<<((int)((size_t)XPROJ * DINNER / 4) + 255) / 256, 256>>>((const float4*)d_in[4], (uint2*)p_wxh, (int)((size_t)XPROJ * DINNER / 4));
    to_half_kernel<<<(DMODEL * DINNER / 4 + 255) / 256, 256>>>((const float4*)d_in[9], (uint2*)p_woh, DMODEL * DINNER / 4);

    // 1) xz = x @ in_proj_w^T  (fp32 out — dt path amplifies rounding via exp(cumsum))
    gemm_f16_mma<<<dim3(2 * DINNER / GBN, NTOK / GBM), 256, GEMM_SMEM>>>(mA1, mB1, p_xz, 2 * DINNER, DMODEL);
    // 2) depthwise conv + bias + silu (fp16 out, 2 ch/thread)
    conv_silu_kernel<<<(NTOK * DINNER / 2) / 256, 256>>>(conv_w, conv_b);
    // 3) proj = conv @ x_proj_w^T (fp32 out)
    gemm_f16_mma<<<dim3((XPROJ + GBN - 1) / GBN, NTOK / GBM), 256, GEMM_SMEM>>>(mA2, mB2, p_proj, XPROJ, DINNER);
    // 4) dt
    dt_kernel<<<NTOK / 4, 256>>>(dt_proj_w, dt_proj_b, A_log);
    // 5) per-chunk local states (split MMA, fp16 states out)
    ssd_states_kernel<<<BATCH * NCHUNK * NHEADS, 256, SST_SMEM>>>();
    // 6) inter-chunk scan (fp16 states, fp32 carry)
    ssd_scan_kernel<<<BATCH * NHEADS * 8, 256>>>();
    // 7) SSD output + gating (split MMA, fp16 out)
    ssd_out_kernel<<<BATCH * NCHUNK * NHEADS, 256, SO_SMEM>>>(Dp);
    // 8) out = Y @ out_proj_w^T (fp32 out)
    gemm_f16_mma<<<dim3(DMODEL / GBN, NTOK / GBM), 256, GEMM_SMEM>>>(mA3, mB3, out, DMODEL, DINNER);
}